// round 2
// baseline (speedup 1.0000x reference)
#include <cuda_runtime.h>
#include <cuda_fp16.h>

// EdgeMLPMPN: out[e] = W3 @ elu(W2 @ elu(W1 @ [x[src];x[tgt]] + b1) + b2) + b3
// Decomposition: W1 @ concat = W1a@x_src + W1b@x_tgt
//   Kernel 1 (precompute): A[n] = W1a@x[n], B[n] = W1b@x[n]
//   Kernel 2 (edge):       h1 = elu(A[src]+B[tgt]+b1); h2 = elu(W2@h1+b2); out = W3@h2+b3
// Edge-index dtype is sniffed at runtime (harness may deliver int32 or int64).

#define C 128
#define NMAX 50000
#define EB 64
#define PC_NODES 32

typedef unsigned long long ull;

__device__ float g_A[(size_t)NMAX * C];   // 25.6 MB scratch
__device__ float g_B[(size_t)NMAX * C];   // 25.6 MB scratch

__device__ __forceinline__ float elu1(float x) {
    return x > 0.0f ? x : expm1f(x);
}

// packed dual-FMA: acc.lo += a.lo*b.lo ; acc.hi += a.hi*b.hi   (sm_100a f32x2 pipe)
__device__ __forceinline__ void ffma2(ull &acc, ull a, ull b) {
    asm("fma.rn.f32x2 %0, %1, %2, %0;" : "+l"(acc) : "l"(a), "l"(b));
}

// true  -> buffer holds int64 indices; false -> packed int32
__device__ __forceinline__ bool idx_is_i64(const void* p) {
    const ull* q = (const ull*)p;
    unsigned hi = 0;
    #pragma unroll
    for (int i = 0; i < 8; i++) hi |= (unsigned)(q[i] >> 32);
    return hi == 0;
}

// ---------------------------------------------------------------------------
// Kernel 1: per-node precompute.  256 thr; lane<->node, warp<->32 out channels.
// ---------------------------------------------------------------------------
#define PC_SMEM ((256 * 128 + PC_NODES * 132) * 4)

__global__ void __launch_bounds__(256, 1)
precompute_kernel(const float* __restrict__ x, const float* __restrict__ W1, int N)
{
    extern __shared__ float sm[];
    float* ws = sm;                    // [256][128]: j<128 -> W1[j][0:128], else W1[j-128][128:256]
    float* xs = sm + 256 * 128;        // [32][132]

    int tid = threadIdx.x;
    int lane = tid & 31, w = tid >> 5;

    const float4* W1v = (const float4*)W1;     // W1 [128][256] row-major: 64 float4 / row
    float4* wsv = (float4*)ws;
    #pragma unroll 4
    for (int idx = tid; idx < 256 * 32; idx += 256) {
        int j = idx >> 5, cidx = idx & 31;
        float4 v = (j < 128) ? W1v[j * 64 + cidx] : W1v[(j - 128) * 64 + 32 + cidx];
        wsv[j * 32 + cidx] = v;
    }
    int n0 = blockIdx.x * PC_NODES;
    for (int idx = tid; idx < PC_NODES * 32; idx += 256) {
        int nl = idx >> 5, cidx = idx & 31;
        int n = min(n0 + nl, N - 1);
        float4 v = ((const float4*)x)[(size_t)n * 32 + cidx];
        *(float4*)&xs[nl * 132 + cidx * 4] = v;
    }
    __syncthreads();

    int j0 = w * 32;
    ull acc2[32];
    #pragma unroll
    for (int i = 0; i < 32; i++) acc2[i] = 0ull;

    for (int k4 = 0; k4 < 32; k4++) {
        float4 xv = *(const float4*)&xs[lane * 132 + k4 * 4];
        ull x01 = ((ull*)&xv)[0], x23 = ((ull*)&xv)[1];
        #pragma unroll
        for (int i = 0; i < 32; i++) {
            float4 wv = *(const float4*)&ws[(j0 + i) * 128 + k4 * 4];
            ffma2(acc2[i], x01, ((ull*)&wv)[0]);
            ffma2(acc2[i], x23, ((ull*)&wv)[1]);
        }
    }

    int n = n0 + lane;
    if (n < N) {
        #pragma unroll
        for (int q = 0; q < 8; q++) {
            float4 v;
            float2 p0 = *(float2*)&acc2[q*4+0];
            float2 p1 = *(float2*)&acc2[q*4+1];
            float2 p2 = *(float2*)&acc2[q*4+2];
            float2 p3 = *(float2*)&acc2[q*4+3];
            v.x = p0.x + p0.y; v.y = p1.x + p1.y;
            v.z = p2.x + p2.y; v.w = p3.x + p3.y;
            int j = j0 + q * 4;
            if (j < 128) *(float4*)&g_A[(size_t)n * C + j]       = v;
            else         *(float4*)&g_B[(size_t)n * C + (j-128)] = v;
        }
    }
}

// ---------------------------------------------------------------------------
// Kernel 2: per-edge fused MLP.  256 thr = 8 warps, EB=64 edges.
// Warp w: edge-group g = w&1 (lane<->edge), channel slice j0 = (w>>1)*32.
// ---------------------------------------------------------------------------
#define ED_SMEM_FLOATS (128*128 + EB*132 + 128 + 128 + 128 + 256 + 128)
#define ED_SMEM (ED_SMEM_FLOATS * 4)

__global__ void __launch_bounds__(256, 2)
edge_kernel(const void* __restrict__ ei,
            const float* __restrict__ W2, const float* __restrict__ b1,
            const float* __restrict__ b2, const float* __restrict__ W3,
            const float* __restrict__ b3, float* __restrict__ out, int E)
{
    extern __shared__ float sm[];
    float* w2s = sm;                            // [128][128]
    float* h1s = sm + 128 * 128;                // [64][132]
    float* b1s = h1s + EB * 132;                // 128
    float* b2s = b1s + 128;                     // 128
    float* w3s = b2s + 128;                     // 128
    float* outp = w3s + 128;                    // [4][64]
    int*   ssrc = (int*)(outp + 256);           // 64
    int*   stgt = ssrc + 64;                    // 64

    int tid = threadIdx.x;
    int lane = tid & 31, w = tid >> 5;
    int E0 = blockIdx.x * EB;

    #pragma unroll 4
    for (int idx = tid; idx < 128 * 32; idx += 256)
        ((float4*)w2s)[idx] = ((const float4*)W2)[idx];
    if (tid < 128) { b1s[tid] = b1[tid]; b2s[tid] = b2[tid]; w3s[tid] = W3[tid]; }
    if (tid < EB) {
        int e = min(E0 + tid, E - 1);
        if (idx_is_i64(ei)) {
            const long long* q = (const long long*)ei;
            ssrc[tid] = (int)q[e];
            stgt[tid] = (int)q[(size_t)E + e];
        } else {
            const int* q = (const int*)ei;
            ssrc[tid] = q[e];
            stgt[tid] = q[(size_t)E + e];
        }
    }
    __syncthreads();

    // Gather + layer 1: h1 = elu(A[src] + B[tgt] + b1)
    for (int idx = tid; idx < EB * 32; idx += 256) {
        int e = idx >> 5, cidx = idx & 31;
        int s = ssrc[e], t = stgt[e];
        float4 a  = ((const float4*)g_A)[(size_t)s * 32 + cidx];
        float4 bb = ((const float4*)g_B)[(size_t)t * 32 + cidx];
        float4 bi = ((const float4*)b1s)[cidx];
        float4 h;
        h.x = elu1(a.x + bb.x + bi.x);
        h.y = elu1(a.y + bb.y + bi.y);
        h.z = elu1(a.z + bb.z + bi.z);
        h.w = elu1(a.w + bb.w + bi.w);
        *(float4*)&h1s[e * 132 + cidx * 4] = h;
    }
    __syncthreads();

    // Layer 2 GEMM: 64 edges x 128 ch, K=128, packed-f32x2 register tiles
    int g = w & 1;
    int j0 = (w >> 1) * 32;
    int el = g * 32 + lane;

    ull acc2[32];
    #pragma unroll
    for (int i = 0; i < 32; i++) acc2[i] = 0ull;

    for (int k4 = 0; k4 < 32; k4++) {
        float4 hv = *(const float4*)&h1s[el * 132 + k4 * 4];
        ull h01 = ((ull*)&hv)[0], h23 = ((ull*)&hv)[1];
        #pragma unroll
        for (int i = 0; i < 32; i++) {
            float4 wv = *(const float4*)&w2s[(j0 + i) * 128 + k4 * 4];
            ffma2(acc2[i], h01, ((ull*)&wv)[0]);
            ffma2(acc2[i], h23, ((ull*)&wv)[1]);
        }
    }

    // Layer-2 epilogue (bias + elu) fused with layer-3 dot
    float part = 0.0f;
    #pragma unroll
    for (int i = 0; i < 32; i++) {
        float2 p = *(float2*)&acc2[i];
        float v = elu1(p.x + p.y + b2s[j0 + i]);
        part = fmaf(w3s[j0 + i], v, part);
    }
    outp[(w >> 1) * 64 + el] = part;
    __syncthreads();

    if (tid < EB) {
        int e = E0 + tid;
        if (e < E)
            out[e] = outp[tid] + outp[64 + tid] + outp[128 + tid] + outp[192 + tid] + b3[0];
    }
}

// ---------------------------------------------------------------------------
extern "C" void kernel_launch(void* const* d_in, const int* in_sizes, int n_in,
                              void* d_out, int out_size)
{
    const float* x  = (const float*)d_in[0];
    const void*  ei = d_in[1];                 // int32 or int64, sniffed on device
    const float* W1 = (const float*)d_in[2];
    const float* b1 = (const float*)d_in[3];
    const float* W2 = (const float*)d_in[4];
    const float* b2 = (const float*)d_in[5];
    const float* W3 = (const float*)d_in[6];
    const float* b3 = (const float*)d_in[7];
    float* out = (float*)d_out;

    int N = in_sizes[0] / C;        // 50000
    int E = in_sizes[1] / 2;        // 640000

    cudaFuncSetAttribute(precompute_kernel, cudaFuncAttributeMaxDynamicSharedMemorySize, PC_SMEM);
    cudaFuncSetAttribute(edge_kernel,       cudaFuncAttributeMaxDynamicSharedMemorySize, ED_SMEM);

    precompute_kernel<<<(N + PC_NODES - 1) / PC_NODES, 256, PC_SMEM>>>(x, W1, N);
    edge_kernel<<<(E + EB - 1) / EB, 256, ED_SMEM>>>(ei, W2, b1, b2, W3, b3, out, E);
}

// round 4
// speedup vs baseline: 1.5912x; 1.5912x over previous
#include <cuda_runtime.h>
#include <cuda_bf16.h>
#include <cstdint>

// EdgeMLPMPN: out[e] = W3 @ elu(W2 @ elu(W1 @ [x[src];x[tgt]] + b1) + b2) + b3
//   Kernel 1 (fp32 SIMT):  A[n] = W1a@x[n], B[n] = W1b@x[n]
//   Kernel 2 (mma.sync bf16, split hi/lo x3 passes):
//       h1 = elu(A[src]+B[tgt]+b1)  -> bf16 hi/lo tiles in smem
//       h2 = W2@h1 via m16n8k16 bf16 MMA (Ahi*Whi + Ahi*Wlo + Alo*Whi)
//       out = W3 @ elu(h2 + b2) + b3   fused in register epilogue
// NOTE: harness compiles at sm_100 (no 'a'): tcgen05 unavailable; mma.sync is baseline PTX.

#define C 128
#define NMAX 50000
#define ET 256                  // edges per block (MMA M)
#define PC_NODES 64
typedef unsigned long long ull;
typedef uint32_t u32;

__device__ float g_A[(size_t)NMAX * C];
__device__ float g_B[(size_t)NMAX * C];

__device__ __forceinline__ float elu1(float x) { return x > 0.0f ? x : expm1f(x); }

__device__ __forceinline__ void ffma2(ull &acc, ull a, ull b) {
    asm("fma.rn.f32x2 %0, %1, %2, %0;" : "+l"(acc) : "l"(a), "l"(b));
}

__device__ __forceinline__ bool idx_is_i64(const void* p) {
    const ull* q = (const ull*)p;
    unsigned hi = 0;
    #pragma unroll
    for (int i = 0; i < 8; i++) hi |= (unsigned)(q[i] >> 32);
    return hi == 0;
}

__device__ __forceinline__ u32 smem_u32(const void* p) {
    u32 a; asm("{ .reg .u64 t; cvta.to.shared.u64 t, %1; cvt.u32.u64 %0, t; }" : "=r"(a) : "l"(p));
    return a;
}

__device__ __forceinline__ void ldsm4(u32 &r0, u32 &r1, u32 &r2, u32 &r3, u32 addr) {
    asm volatile("ldmatrix.sync.aligned.m8n8.x4.shared.b16 {%0,%1,%2,%3}, [%4];"
                 : "=r"(r0), "=r"(r1), "=r"(r2), "=r"(r3) : "r"(addr));
}

__device__ __forceinline__ void mma_bf16(float* d, u32 a0, u32 a1, u32 a2, u32 a3,
                                         u32 b0, u32 b1) {
    asm volatile("mma.sync.aligned.m16n8k16.row.col.f32.bf16.bf16.f32 "
                 "{%0,%1,%2,%3}, {%4,%5,%6,%7}, {%8,%9}, {%0,%1,%2,%3};"
                 : "+f"(d[0]), "+f"(d[1]), "+f"(d[2]), "+f"(d[3])
                 : "r"(a0), "r"(a1), "r"(a2), "r"(a3), "r"(b0), "r"(b1));
}

// split fp32 -> (hi, lo) bf16 bit patterns; f ~= hi + lo with |lo| <= 2^-9 |f|
__device__ __forceinline__ void split_bf16(float f, u32 &hi, u32 &lo) {
    __nv_bfloat16 h = __float2bfloat16(f);
    float r = f - __bfloat162float(h);
    __nv_bfloat16 l = __float2bfloat16(r);
    hi = (u32)__bfloat16_as_ushort(h);
    lo = (u32)__bfloat16_as_ushort(l);
}
__device__ __forceinline__ ull pack4(u32 a, u32 b, u32 c, u32 d) {
    return (ull)(a | (b << 16)) | ((ull)(c | (d << 16)) << 32);
}

// ---------------------------------------------------------------------------
// Kernel 1: per-node precompute (fp32, f32x2-packed FMA tiling).
// 512 thr = 16 warps; warp -> 16 out channels, thread -> 2 nodes.
// ---------------------------------------------------------------------------
#define PC_SMEM ((256 * 128 + PC_NODES * 132) * 4)

__global__ void __launch_bounds__(512, 1)
precompute_kernel(const float* __restrict__ x, const float* __restrict__ W1, int N)
{
    extern __shared__ float sm[];
    float* ws = sm;                    // [256][128]
    float* xs = sm + 256 * 128;        // [64][132]

    int tid = threadIdx.x;
    int lane = tid & 31, w = tid >> 5;

    const float4* W1v = (const float4*)W1;
    float4* wsv = (float4*)ws;
    #pragma unroll 4
    for (int idx = tid; idx < 256 * 32; idx += 512) {
        int j = idx >> 5, c = idx & 31;
        float4 v = (j < 128) ? W1v[j * 64 + c] : W1v[(j - 128) * 64 + 32 + c];
        wsv[j * 32 + c] = v;
    }
    int n0 = blockIdx.x * PC_NODES;
    for (int idx = tid; idx < PC_NODES * 32; idx += 512) {
        int nl = idx >> 5, c = idx & 31;
        int n = min(n0 + nl, N - 1);
        float4 v = ((const float4*)x)[(size_t)n * 32 + c];
        *(float4*)&xs[nl * 132 + c * 4] = v;
    }
    __syncthreads();

    int j0 = w * 16;
    ull acc[2][16];
    #pragma unroll
    for (int r = 0; r < 2; r++)
        #pragma unroll
        for (int i = 0; i < 16; i++) acc[r][i] = 0ull;

    for (int k4 = 0; k4 < 32; k4++) {
        float4 x0 = *(const float4*)&xs[lane * 132 + k4 * 4];
        float4 x1 = *(const float4*)&xs[(lane + 32) * 132 + k4 * 4];
        ull a01 = ((ull*)&x0)[0], a23 = ((ull*)&x0)[1];
        ull b01 = ((ull*)&x1)[0], b23 = ((ull*)&x1)[1];
        #pragma unroll
        for (int i = 0; i < 16; i++) {
            float4 wv = *(const float4*)&ws[(j0 + i) * 128 + k4 * 4];
            ull w01 = ((ull*)&wv)[0], w23 = ((ull*)&wv)[1];
            ffma2(acc[0][i], a01, w01); ffma2(acc[0][i], a23, w23);
            ffma2(acc[1][i], b01, w01); ffma2(acc[1][i], b23, w23);
        }
    }

    #pragma unroll
    for (int r = 0; r < 2; r++) {
        int n = n0 + lane + r * 32;
        if (n < N) {
            #pragma unroll
            for (int q = 0; q < 4; q++) {
                float4 v;
                float2 p0 = *(float2*)&acc[r][q*4+0];
                float2 p1 = *(float2*)&acc[r][q*4+1];
                float2 p2 = *(float2*)&acc[r][q*4+2];
                float2 p3 = *(float2*)&acc[r][q*4+3];
                v.x = p0.x + p0.y; v.y = p1.x + p1.y;
                v.z = p2.x + p2.y; v.w = p3.x + p3.y;
                int j = j0 + q * 4;
                if (j0 < 128) *(float4*)&g_A[(size_t)n * C + j]         = v;
                else          *(float4*)&g_B[(size_t)n * C + (j - 128)] = v;
            }
        }
    }
}

// ---------------------------------------------------------------------------
// Kernel 2: edge tile, mma.sync split-bf16. 512 thr = 16 warps, 256 edges.
// smem rows padded to 272B (17x16B): ldmatrix row-pointers conflict-free.
// Warp (wm=w>>2, wn=w&3): output tile rows [wm*64,+64), cols [wn*32,+32).
// ---------------------------------------------------------------------------
#define HSTRIDE 272
#define OFF_HHI  0                         // [256][272] bf16 hi  (69632)
#define OFF_HLO  69632                     // lo
#define OFF_WHI  139264                    // [128][272] bf16 hi  (34816)
#define OFF_WLO  174080
#define OFF_B1   208896
#define OFF_B2   209408
#define OFF_W3   209920
#define OFF_PART 210432                    // [4][256] f32 (4096)
#define OFF_SRC  214528                    // [256] i32
#define OFF_TGT  215552
#define ED_SMEM  216576

__global__ void __launch_bounds__(512, 1)
edge_kernel(const void* __restrict__ ei,
            const float* __restrict__ W2, const float* __restrict__ b1,
            const float* __restrict__ b2, const float* __restrict__ W3,
            const float* __restrict__ b3, float* __restrict__ out, int E)
{
    extern __shared__ __align__(128) char smc[];
    u32 sb = smem_u32(smc);
    float* b1s = (float*)(smc + OFF_B1);
    float* b2s = (float*)(smc + OFF_B2);
    float* w3s = (float*)(smc + OFF_W3);
    float* part = (float*)(smc + OFF_PART);
    int* srcs = (int*)(smc + OFF_SRC);
    int* tgts = (int*)(smc + OFF_TGT);

    int tid = threadIdx.x;
    int lane = tid & 31, w = tid >> 5;
    int E0 = blockIdx.x * ET;

    if (tid < 128) { b1s[tid] = b1[tid]; b2s[tid] = b2[tid]; w3s[tid] = W3[tid]; }
    if (tid < ET) {
        int e = min(E0 + tid, E - 1);
        if (idx_is_i64(ei)) {
            const long long* q = (const long long*)ei;
            srcs[tid] = (int)q[e]; tgts[tid] = (int)q[(size_t)E + e];
        } else {
            const int* q = (const int*)ei;
            srcs[tid] = q[e]; tgts[tid] = q[(size_t)E + e];
        }
    }
    __syncthreads();

    // Stage W2 split: row j, k contiguous (col-major B operand for mma row.col)
    const float4* W2v = (const float4*)W2;
    for (int idx = tid; idx < 128 * 32; idx += 512) {
        int j = idx >> 5, c4 = idx & 31;
        float4 v = W2v[idx];
        u32 h0,l0,h1,l1,h2,l2,h3,l3;
        split_bf16(v.x, h0, l0); split_bf16(v.y, h1, l1);
        split_bf16(v.z, h2, l2); split_bf16(v.w, h3, l3);
        *(ull*)(smc + OFF_WHI + j * HSTRIDE + c4 * 8) = pack4(h0, h1, h2, h3);
        *(ull*)(smc + OFF_WLO + j * HSTRIDE + c4 * 8) = pack4(l0, l1, l2, l3);
    }
    // Gather + layer 1 + split: row e, k contiguous (row-major A operand)
    for (int idx = tid; idx < ET * 32; idx += 512) {
        int e = idx >> 5, c4 = idx & 31;
        int s = srcs[e], t = tgts[e];
        float4 a  = ((const float4*)g_A)[(size_t)s * 32 + c4];
        float4 bb = ((const float4*)g_B)[(size_t)t * 32 + c4];
        float4 bi = ((const float4*)b1s)[c4];
        float hx = elu1(a.x + bb.x + bi.x);
        float hy = elu1(a.y + bb.y + bi.y);
        float hz = elu1(a.z + bb.z + bi.z);
        float hw = elu1(a.w + bb.w + bi.w);
        u32 h0,l0,h1,l1,h2,l2,h3,l3;
        split_bf16(hx, h0, l0); split_bf16(hy, h1, l1);
        split_bf16(hz, h2, l2); split_bf16(hw, h3, l3);
        *(ull*)(smc + OFF_HHI + e * HSTRIDE + c4 * 8) = pack4(h0, h1, h2, h3);
        *(ull*)(smc + OFF_HLO + e * HSTRIDE + c4 * 8) = pack4(l0, l1, l2, l3);
    }
    __syncthreads();

    // GEMM: D[256x128] = Hhi@Whi^T + Hhi@Wlo^T + Hlo@Whi^T
    int wm = w >> 2, wn = w & 3;
    int g = lane >> 3, lr = lane & 7;
    int arow = (g & 1) * 8 + lr;       // 0..15 within-tile row for ldmatrix
    u32 kh = (u32)((g >> 1) * 16);     // 16B half select

    u32 aBaseHi = sb + OFF_HHI + (wm * 64 + arow) * HSTRIDE + kh;
    u32 aBaseLo = sb + OFF_HLO + (wm * 64 + arow) * HSTRIDE + kh;
    u32 bBaseHi = sb + OFF_WHI + (wn * 32 + arow) * HSTRIDE + kh;
    u32 bBaseLo = sb + OFF_WLO + (wn * 32 + arow) * HSTRIDE + kh;

    float acc[4][4][4];
    #pragma unroll
    for (int mi = 0; mi < 4; mi++)
        #pragma unroll
        for (int ni = 0; ni < 4; ni++)
            #pragma unroll
            for (int q = 0; q < 4; q++) acc[mi][ni][q] = 0.0f;

    #pragma unroll
    for (int ks = 0; ks < 8; ks++) {
        u32 ko = (u32)(ks * 32);
        u32 bh[4][2], bl[4][2];
        { u32 r0,r1,r2,r3; ldsm4(r0,r1,r2,r3, bBaseHi + ko);
          bh[0][0]=r0; bh[0][1]=r2; bh[1][0]=r1; bh[1][1]=r3; }
        { u32 r0,r1,r2,r3; ldsm4(r0,r1,r2,r3, bBaseHi + 16*HSTRIDE + ko);
          bh[2][0]=r0; bh[2][1]=r2; bh[3][0]=r1; bh[3][1]=r3; }
        { u32 r0,r1,r2,r3; ldsm4(r0,r1,r2,r3, bBaseLo + ko);
          bl[0][0]=r0; bl[0][1]=r2; bl[1][0]=r1; bl[1][1]=r3; }
        { u32 r0,r1,r2,r3; ldsm4(r0,r1,r2,r3, bBaseLo + 16*HSTRIDE + ko);
          bl[2][0]=r0; bl[2][1]=r2; bl[3][0]=r1; bl[3][1]=r3; }
        #pragma unroll
        for (int mi = 0; mi < 4; mi++) {
            u32 a0,a1,a2,a3, c0,c1,c2,c3;
            ldsm4(a0,a1,a2,a3, aBaseHi + mi * 16 * HSTRIDE + ko);
            ldsm4(c0,c1,c2,c3, aBaseLo + mi * 16 * HSTRIDE + ko);
            #pragma unroll
            for (int ni = 0; ni < 4; ni++) {
                mma_bf16(acc[mi][ni], a0,a1,a2,a3, bh[ni][0], bh[ni][1]);
                mma_bf16(acc[mi][ni], a0,a1,a2,a3, bl[ni][0], bl[ni][1]);
                mma_bf16(acc[mi][ni], c0,c1,c2,c3, bh[ni][0], bh[ni][1]);
            }
        }
    }

    // Epilogue: v = elu(h2 + b2); per-row dot with W3; reduce 4 lanes -> row partial
    #pragma unroll
    for (int mi = 0; mi < 4; mi++) {
        float p0 = 0.0f, p1 = 0.0f;
        #pragma unroll
        for (int ni = 0; ni < 4; ni++) {
            int j = wn * 32 + ni * 8 + (lane & 3) * 2;
            float w3a = w3s[j], w3b = w3s[j + 1];
            float b2a = b2s[j], b2b = b2s[j + 1];
            p0 = fmaf(w3a, elu1(acc[mi][ni][0] + b2a), p0);
            p0 = fmaf(w3b, elu1(acc[mi][ni][1] + b2b), p0);
            p1 = fmaf(w3a, elu1(acc[mi][ni][2] + b2a), p1);
            p1 = fmaf(w3b, elu1(acc[mi][ni][3] + b2b), p1);
        }
        p0 += __shfl_xor_sync(0xFFFFFFFFu, p0, 1);
        p0 += __shfl_xor_sync(0xFFFFFFFFu, p0, 2);
        p1 += __shfl_xor_sync(0xFFFFFFFFu, p1, 1);
        p1 += __shfl_xor_sync(0xFFFFFFFFu, p1, 2);
        if ((lane & 3) == 0) {
            int r = wm * 64 + mi * 16 + (lane >> 2);
            part[wn * 256 + r]     = p0;
            part[wn * 256 + r + 8] = p1;
        }
    }
    __syncthreads();

    if (tid < ET) {
        int e = E0 + tid;
        if (e < E)
            out[e] = part[tid] + part[256 + tid] + part[512 + tid] + part[768 + tid] + b3[0];
    }
}

// ---------------------------------------------------------------------------
extern "C" void kernel_launch(void* const* d_in, const int* in_sizes, int n_in,
                              void* d_out, int out_size)
{
    const float* x  = (const float*)d_in[0];
    const void*  ei = d_in[1];
    const float* W1 = (const float*)d_in[2];
    const float* b1 = (const float*)d_in[3];
    const float* W2 = (const float*)d_in[4];
    const float* b2 = (const float*)d_in[5];
    const float* W3 = (const float*)d_in[6];
    const float* b3 = (const float*)d_in[7];
    float* out = (float*)d_out;

    int N = in_sizes[0] / C;        // 50000
    int E = in_sizes[1] / 2;        // 640000

    cudaFuncSetAttribute(precompute_kernel, cudaFuncAttributeMaxDynamicSharedMemorySize, PC_SMEM);
    cudaFuncSetAttribute(edge_kernel,       cudaFuncAttributeMaxDynamicSharedMemorySize, ED_SMEM);

    precompute_kernel<<<(N + PC_NODES - 1) / PC_NODES, 512, PC_SMEM>>>(x, W1, N);
    edge_kernel<<<(E + ET - 1) / ET, 512, ED_SMEM>>>(ei, W2, b1, b2, W3, b3, out, E);
}

// round 5
// speedup vs baseline: 1.6787x; 1.0550x over previous
#include <cuda_runtime.h>
#include <cuda_bf16.h>
#include <cstdint>

// EdgeMLPMPN: out[e] = W3 @ elu(W2 @ elu(W1 @ [x[src];x[tgt]] + b1) + b2) + b3
//   Kernel 1 (fp32 SIMT):  A[n] = W1a@x[n], B[n] = W1b@x[n]
//   Kernel 2 (warp-specialized pipeline):
//       producers (warps 0-7): gather + elu + split-bf16 -> double-buffered H tiles
//       consumers (warps 8-15): 3-pass split-bf16 mma.sync + fused epilogue
// Compiled at sm_100 (no 'a'): mma.sync/ldmatrix only, no tcgen05.

#define C 128
#define NMAX 50000
#define ET 128                  // edges per tile
#define NBUF 2
#define EDGE_GRID 296
#define PC_NODES 64
typedef unsigned long long ull;
typedef uint32_t u32;

__device__ float g_A[(size_t)NMAX * C];
__device__ float g_B[(size_t)NMAX * C];

__device__ __forceinline__ float elu_fast(float x) {
    return x > 0.0f ? x : (__expf(x) - 1.0f);
}

__device__ __forceinline__ void ffma2(ull &acc, ull a, ull b) {
    asm("fma.rn.f32x2 %0, %1, %2, %0;" : "+l"(acc) : "l"(a), "l"(b));
}

__device__ __forceinline__ bool idx_is_i64(const void* p) {
    const ull* q = (const ull*)p;
    unsigned hi = 0;
    #pragma unroll
    for (int i = 0; i < 8; i++) hi |= (unsigned)(q[i] >> 32);
    return hi == 0;
}

__device__ __forceinline__ u32 smem_u32(const void* p) {
    u32 a; asm("{ .reg .u64 t; cvta.to.shared.u64 t, %1; cvt.u32.u64 %0, t; }" : "=r"(a) : "l"(p));
    return a;
}

__device__ __forceinline__ void ldsm4(u32 &r0, u32 &r1, u32 &r2, u32 &r3, u32 addr) {
    asm volatile("ldmatrix.sync.aligned.m8n8.x4.shared.b16 {%0,%1,%2,%3}, [%4];"
                 : "=r"(r0), "=r"(r1), "=r"(r2), "=r"(r3) : "r"(addr));
}

__device__ __forceinline__ void mma_bf16(float* d, u32 a0, u32 a1, u32 a2, u32 a3,
                                         u32 b0, u32 b1) {
    asm volatile("mma.sync.aligned.m16n8k16.row.col.f32.bf16.bf16.f32 "
                 "{%0,%1,%2,%3}, {%4,%5,%6,%7}, {%8,%9}, {%0,%1,%2,%3};"
                 : "+f"(d[0]), "+f"(d[1]), "+f"(d[2]), "+f"(d[3])
                 : "r"(a0), "r"(a1), "r"(a2), "r"(a3), "r"(b0), "r"(b1));
}

// pack two floats to bf16x2 (rn); first arg -> low half
__device__ __forceinline__ u32 cvt_bf2(float lo, float hi) {
    u32 r; asm("cvt.rn.bf16x2.f32 %0, %1, %2;" : "=r"(r) : "f"(hi), "f"(lo));
    return r;
}

// split float4 -> packed hi bf16x4 (as ull) and lo bf16x4
__device__ __forceinline__ void split4(float4 h, ull &hiP, ull &loP) {
    u32 hxy = cvt_bf2(h.x, h.y);
    u32 hzw = cvt_bf2(h.z, h.w);
    float rx = h.x - __uint_as_float(hxy << 16);
    float ry = h.y - __uint_as_float(hxy & 0xFFFF0000u);
    float rz = h.z - __uint_as_float(hzw << 16);
    float rw = h.w - __uint_as_float(hzw & 0xFFFF0000u);
    u32 lxy = cvt_bf2(rx, ry);
    u32 lzw = cvt_bf2(rz, rw);
    hiP = (ull)hxy | ((ull)hzw << 32);
    loP = (ull)lxy | ((ull)lzw << 32);
}

#define BAR_SYNC(id, n)   asm volatile("bar.sync %0, %1;"   :: "r"(id), "r"(n) : "memory")
#define BAR_ARRIVE(id, n) asm volatile("bar.arrive %0, %1;" :: "r"(id), "r"(n) : "memory")
#define MEMBAR_CTA()      asm volatile("membar.cta;" ::: "memory")

// ---------------------------------------------------------------------------
// Kernel 1: per-node precompute (fp32 f32x2 FMA). 512 thr = 16 warps.
// ---------------------------------------------------------------------------
#define PC_SMEM ((256 * 128 + PC_NODES * 132) * 4)

__global__ void __launch_bounds__(512, 1)
precompute_kernel(const float* __restrict__ x, const float* __restrict__ W1, int N)
{
    extern __shared__ float sm[];
    float* ws = sm;                    // [256][128]
    float* xs = sm + 256 * 128;        // [64][132]

    int tid = threadIdx.x;
    int lane = tid & 31, w = tid >> 5;

    const float4* W1v = (const float4*)W1;
    float4* wsv = (float4*)ws;
    #pragma unroll 4
    for (int idx = tid; idx < 256 * 32; idx += 512) {
        int j = idx >> 5, c = idx & 31;
        float4 v = (j < 128) ? W1v[j * 64 + c] : W1v[(j - 128) * 64 + 32 + c];
        wsv[j * 32 + c] = v;
    }
    int n0 = blockIdx.x * PC_NODES;
    for (int idx = tid; idx < PC_NODES * 32; idx += 512) {
        int nl = idx >> 5, c = idx & 31;
        int n = min(n0 + nl, N - 1);
        float4 v = ((const float4*)x)[(size_t)n * 32 + c];
        *(float4*)&xs[nl * 132 + c * 4] = v;
    }
    __syncthreads();

    int j0 = w * 16;
    ull acc[2][16];
    #pragma unroll
    for (int r = 0; r < 2; r++)
        #pragma unroll
        for (int i = 0; i < 16; i++) acc[r][i] = 0ull;

    for (int k4 = 0; k4 < 32; k4++) {
        float4 x0 = *(const float4*)&xs[lane * 132 + k4 * 4];
        float4 x1 = *(const float4*)&xs[(lane + 32) * 132 + k4 * 4];
        ull a01 = ((ull*)&x0)[0], a23 = ((ull*)&x0)[1];
        ull b01 = ((ull*)&x1)[0], b23 = ((ull*)&x1)[1];
        #pragma unroll
        for (int i = 0; i < 16; i++) {
            float4 wv = *(const float4*)&ws[(j0 + i) * 128 + k4 * 4];
            ull w01 = ((ull*)&wv)[0], w23 = ((ull*)&wv)[1];
            ffma2(acc[0][i], a01, w01); ffma2(acc[0][i], a23, w23);
            ffma2(acc[1][i], b01, w01); ffma2(acc[1][i], b23, w23);
        }
    }

    #pragma unroll
    for (int r = 0; r < 2; r++) {
        int n = n0 + lane + r * 32;
        if (n < N) {
            #pragma unroll
            for (int q = 0; q < 4; q++) {
                float4 v;
                float2 p0 = *(float2*)&acc[r][q*4+0];
                float2 p1 = *(float2*)&acc[r][q*4+1];
                float2 p2 = *(float2*)&acc[r][q*4+2];
                float2 p3 = *(float2*)&acc[r][q*4+3];
                v.x = p0.x + p0.y; v.y = p1.x + p1.y;
                v.z = p2.x + p2.y; v.w = p3.x + p3.y;
                int j = j0 + q * 4;
                if (j0 < 128) *(float4*)&g_A[(size_t)n * C + j]         = v;
                else          *(float4*)&g_B[(size_t)n * C + (j - 128)] = v;
            }
        }
    }
}

// ---------------------------------------------------------------------------
// Kernel 2: warp-specialized pipelined edge MLP.
// smem layout (bytes):
// ---------------------------------------------------------------------------
#define HSTRIDE 272
#define HTILE   (ET * HSTRIDE)            // 34816
#define OFF_WHI  0
#define OFF_WLO  34816
#define OFF_H    69632                    // buf b: HHI @ +b*2*HTILE, HLO @ +HTILE
#define OFF_B1   208896
#define OFF_B2   209408
#define OFF_W3   209920
#define OFF_PART 210432                   // [2 parity][2 wh][128] f32 = 2048
#define OFF_B3   212480
#define ED_SMEM  212608

// named barriers: READY(b)=1+b, FREE(b)=3+b, consumer-only=5
#define NTILES(E) (((E) + ET - 1) / ET)

__global__ void __launch_bounds__(512, 1)
edge_kernel(const void* __restrict__ ei,
            const float* __restrict__ W2, const float* __restrict__ b1,
            const float* __restrict__ b2, const float* __restrict__ W3,
            const float* __restrict__ b3, float* __restrict__ out, int E)
{
    extern __shared__ __align__(128) char smc[];
    u32 sb = smem_u32(smc);
    float* b1s = (float*)(smc + OFF_B1);
    float* b2s = (float*)(smc + OFF_B2);
    float* w3s = (float*)(smc + OFF_W3);
    float* part = (float*)(smc + OFF_PART);

    int tid = threadIdx.x;
    int lane = tid & 31, w = tid >> 5;
    bool i64 = idx_is_i64(ei);

    // ---- stage constants + split W2 (all threads) ----
    if (tid < 128) { b1s[tid] = b1[tid]; b2s[tid] = b2[tid]; w3s[tid] = W3[tid]; }
    if (tid == 0) *(float*)(smc + OFF_B3) = b3[0];
    const float4* W2v = (const float4*)W2;
    for (int idx = tid; idx < 128 * 32; idx += 512) {
        int j = idx >> 5, c4 = idx & 31;
        ull hp, lp;
        split4(W2v[idx], hp, lp);
        *(ull*)(smc + OFF_WHI + j * HSTRIDE + c4 * 8) = hp;
        *(ull*)(smc + OFF_WLO + j * HSTRIDE + c4 * 8) = lp;
    }
    __syncthreads();

    int ntiles = NTILES(E);

    if (w < 8) {
        // ================= PRODUCERS (256 threads) =================
        int el   = tid >> 1;            // 0..127  edge-in-tile
        int c4b  = (tid & 1) * 16;      // channel float4 base
        int i = 0;
        for (int t = blockIdx.x; t < ntiles; t += EDGE_GRID, i++) {
            int b = i & 1;
            if (i >= NBUF) BAR_SYNC(3 + b, 512);
            int e = min(t * ET + el, E - 1);
            int s, tg;
            if (i64) {
                const long long* q = (const long long*)ei;
                s = (int)q[e]; tg = (int)q[(size_t)E + e];
            } else {
                const int* q = (const int*)ei;
                s = q[e]; tg = q[(size_t)E + e];
            }
            const float4* Ar = (const float4*)g_A + (size_t)s * 32 + c4b;
            const float4* Br = (const float4*)g_B + (size_t)tg * 32 + c4b;
            const float4* bi4 = (const float4*)b1s + c4b;
            char* hhi = smc + OFF_H + b * 2 * HTILE + el * HSTRIDE + c4b * 8;
            char* hlo = hhi + HTILE;
            #pragma unroll 4
            for (int c = 0; c < 16; c++) {
                float4 a = Ar[c], bb = Br[c], bi = bi4[c];
                float4 h;
                h.x = elu_fast(a.x + bb.x + bi.x);
                h.y = elu_fast(a.y + bb.y + bi.y);
                h.z = elu_fast(a.z + bb.z + bi.z);
                h.w = elu_fast(a.w + bb.w + bi.w);
                ull hp, lp;
                split4(h, hp, lp);
                *(ull*)(hhi + c * 8) = hp;
                *(ull*)(hlo + c * 8) = lp;
            }
            MEMBAR_CTA();
            BAR_ARRIVE(1 + b, 512);
        }
    } else {
        // ================= CONSUMERS (256 threads) =================
        int cw = w - 8;
        int wm = cw & 3;                  // row block [wm*32, +32)
        int wh = cw >> 2;                 // col half  [wh*64, +64)
        int g  = lane >> 3, lr = lane & 7;
        int arow = (g & 1) * 8 + lr;
        u32 kh = (u32)((g >> 1) * 16);

        u32 bBaseHi = sb + OFF_WHI + (wh * 64 + arow) * HSTRIDE + kh;
        u32 bBaseLo = sb + OFF_WLO + (wh * 64 + arow) * HSTRIDE + kh;

        float b3v = *(float*)(smc + OFF_B3);
        int i = 0;
        for (int t = blockIdx.x; t < ntiles; t += EDGE_GRID, i++) {
            int b = i & 1;
            BAR_SYNC(1 + b, 512);

            u32 aBaseHi = sb + OFF_H + b * 2 * HTILE + (wm * 32 + arow) * HSTRIDE + kh;
            u32 aBaseLo = aBaseHi + (u32)HTILE;

            float acc[2][8][4];
            #pragma unroll
            for (int mi = 0; mi < 2; mi++)
                #pragma unroll
                for (int ni = 0; ni < 8; ni++)
                    #pragma unroll
                    for (int q = 0; q < 4; q++) acc[mi][ni][q] = 0.0f;

            #pragma unroll
            for (int ks = 0; ks < 8; ks++) {
                u32 ko = (u32)(ks * 32);
                u32 bh[8][2], bl[8][2];
                #pragma unroll
                for (int gB = 0; gB < 4; gB++) {
                    u32 r0,r1,r2,r3;
                    ldsm4(r0,r1,r2,r3, bBaseHi + gB * 16 * HSTRIDE + ko);
                    bh[gB*2][0]=r0; bh[gB*2][1]=r2; bh[gB*2+1][0]=r1; bh[gB*2+1][1]=r3;
                }
                #pragma unroll
                for (int gB = 0; gB < 4; gB++) {
                    u32 r0,r1,r2,r3;
                    ldsm4(r0,r1,r2,r3, bBaseLo + gB * 16 * HSTRIDE + ko);
                    bl[gB*2][0]=r0; bl[gB*2][1]=r2; bl[gB*2+1][0]=r1; bl[gB*2+1][1]=r3;
                }
                #pragma unroll
                for (int mi = 0; mi < 2; mi++) {
                    u32 a0,a1,a2,a3, c0,c1,c2,c3;
                    ldsm4(a0,a1,a2,a3, aBaseHi + mi * 16 * HSTRIDE + ko);
                    ldsm4(c0,c1,c2,c3, aBaseLo + mi * 16 * HSTRIDE + ko);
                    #pragma unroll
                    for (int ni = 0; ni < 8; ni++) {
                        mma_bf16(acc[mi][ni], a0,a1,a2,a3, bh[ni][0], bh[ni][1]);
                        mma_bf16(acc[mi][ni], a0,a1,a2,a3, bl[ni][0], bl[ni][1]);
                        mma_bf16(acc[mi][ni], c0,c1,c2,c3, bh[ni][0], bh[ni][1]);
                    }
                }
            }
            BAR_ARRIVE(3 + b, 512);        // buffer free; epilogue uses regs only

            int par = i & 1;
            float* pp = part + par * 256 + wh * 128;
            #pragma unroll
            for (int mi = 0; mi < 2; mi++) {
                float p0 = 0.0f, p1 = 0.0f;
                #pragma unroll
                for (int ni = 0; ni < 8; ni++) {
                    int j = wh * 64 + ni * 8 + (lane & 3) * 2;
                    float w3a = w3s[j], w3b = w3s[j + 1];
                    float b2a = b2s[j], b2b = b2s[j + 1];
                    p0 = fmaf(w3a, elu_fast(acc[mi][ni][0] + b2a), p0);
                    p0 = fmaf(w3b, elu_fast(acc[mi][ni][1] + b2b), p0);
                    p1 = fmaf(w3a, elu_fast(acc[mi][ni][2] + b2a), p1);
                    p1 = fmaf(w3b, elu_fast(acc[mi][ni][3] + b2b), p1);
                }
                p0 += __shfl_xor_sync(0xFFFFFFFFu, p0, 1);
                p0 += __shfl_xor_sync(0xFFFFFFFFu, p0, 2);
                p1 += __shfl_xor_sync(0xFFFFFFFFu, p1, 1);
                p1 += __shfl_xor_sync(0xFFFFFFFFu, p1, 2);
                if ((lane & 3) == 0) {
                    int r = wm * 32 + mi * 16 + (lane >> 2);
                    pp[r]     = p0;
                    pp[r + 8] = p1;
                }
            }
            BAR_SYNC(5, 256);               // consumer-only
            int ctid = tid - 256;
            if (ctid < 128) {
                int e = t * ET + ctid;
                if (e < E)
                    out[e] = part[par * 256 + ctid] + part[par * 256 + 128 + ctid] + b3v;
            }
        }
    }
}

// ---------------------------------------------------------------------------
extern "C" void kernel_launch(void* const* d_in, const int* in_sizes, int n_in,
                              void* d_out, int out_size)
{
    const float* x  = (const float*)d_in[0];
    const void*  ei = d_in[1];
    const float* W1 = (const float*)d_in[2];
    const float* b1 = (const float*)d_in[3];
    const float* W2 = (const float*)d_in[4];
    const float* b2 = (const float*)d_in[5];
    const float* W3 = (const float*)d_in[6];
    const float* b3 = (const float*)d_in[7];
    float* out = (float*)d_out;

    int N = in_sizes[0] / C;        // 50000
    int E = in_sizes[1] / 2;        // 640000

    cudaFuncSetAttribute(precompute_kernel, cudaFuncAttributeMaxDynamicSharedMemorySize, PC_SMEM);
    cudaFuncSetAttribute(edge_kernel,       cudaFuncAttributeMaxDynamicSharedMemorySize, ED_SMEM);

    precompute_kernel<<<(N + PC_NODES - 1) / PC_NODES, 512, PC_SMEM>>>(x, W1, N);
    edge_kernel<<<EDGE_GRID, 512, ED_SMEM>>>(ei, W2, b1, b2, W3, b3, out, E);
}

// round 8
// speedup vs baseline: 2.7033x; 1.6103x over previous
#include <cuda_runtime.h>
#include <cuda_bf16.h>
#include <cstdint>

// EdgeMLPMPN: out[e] = W3 @ elu(W2 @ elu(W1 @ [x[src];x[tgt]] + b1) + b2) + b3
//   Kernel 1 (split-bf16 mma.sync GEMM): [A|B](n) = [W1a|W1b] @ x[n]
//   Kernel 2 (warp-specialized pipeline):
//       producers (warps 0-7): line-coalesced gather + elu + split-bf16 -> 2-buffered H tiles
//       consumers (warps 8-15): 3-pass split-bf16 mma.sync + fused epilogue
// Compiled at sm_100 (no 'a'): mma.sync/ldmatrix only, no tcgen05.

#define C 128
#define NMAX 50000
#define ET 128
#define NBUF 2
#define EDGE_GRID 296
typedef unsigned long long ull;
typedef uint32_t u32;

__device__ float g_A[(size_t)NMAX * C];
__device__ float g_B[(size_t)NMAX * C];

__device__ __forceinline__ float elu_fast(float x) {
    return x > 0.0f ? x : (__expf(x) - 1.0f);
}

__device__ __forceinline__ bool idx_is_i64(const void* p) {
    const ull* q = (const ull*)p;
    unsigned hi = 0;
    #pragma unroll
    for (int i = 0; i < 8; i++) hi |= (unsigned)(q[i] >> 32);
    return hi == 0;
}

__device__ __forceinline__ u32 smem_u32(const void* p) {
    u32 a; asm("{ .reg .u64 t; cvta.to.shared.u64 t, %1; cvt.u32.u64 %0, t; }" : "=r"(a) : "l"(p));
    return a;
}

__device__ __forceinline__ void ldsm4(u32 &r0, u32 &r1, u32 &r2, u32 &r3, u32 addr) {
    asm volatile("ldmatrix.sync.aligned.m8n8.x4.shared.b16 {%0,%1,%2,%3}, [%4];"
                 : "=r"(r0), "=r"(r1), "=r"(r2), "=r"(r3) : "r"(addr));
}

__device__ __forceinline__ void mma_bf16(float* d, u32 a0, u32 a1, u32 a2, u32 a3,
                                         u32 b0, u32 b1) {
    asm volatile("mma.sync.aligned.m16n8k16.row.col.f32.bf16.bf16.f32 "
                 "{%0,%1,%2,%3}, {%4,%5,%6,%7}, {%8,%9}, {%0,%1,%2,%3};"
                 : "+f"(d[0]), "+f"(d[1]), "+f"(d[2]), "+f"(d[3])
                 : "r"(a0), "r"(a1), "r"(a2), "r"(a3), "r"(b0), "r"(b1));
}

__device__ __forceinline__ u32 cvt_bf2(float lo, float hi) {
    u32 r; asm("cvt.rn.bf16x2.f32 %0, %1, %2;" : "=r"(r) : "f"(hi), "f"(lo));
    return r;
}

__device__ __forceinline__ void split4(float4 h, ull &hiP, ull &loP) {
    u32 hxy = cvt_bf2(h.x, h.y);
    u32 hzw = cvt_bf2(h.z, h.w);
    float rx = h.x - __uint_as_float(hxy << 16);
    float ry = h.y - __uint_as_float(hxy & 0xFFFF0000u);
    float rz = h.z - __uint_as_float(hzw << 16);
    float rw = h.w - __uint_as_float(hzw & 0xFFFF0000u);
    u32 lxy = cvt_bf2(rx, ry);
    u32 lzw = cvt_bf2(rz, rw);
    hiP = (ull)hxy | ((ull)hzw << 32);
    loP = (ull)lxy | ((ull)lzw << 32);
}

#define BAR_SYNC(id, n)   asm volatile("bar.sync %0, %1;"   :: "r"(id), "r"(n) : "memory")
#define BAR_ARRIVE(id, n) asm volatile("bar.arrive %0, %1;" :: "r"(id), "r"(n) : "memory")
#define MEMBAR_CTA()      asm volatile("membar.cta;" ::: "memory")

#define HSTRIDE 272

// ---------------------------------------------------------------------------
// Kernel 1: node precompute as split-bf16 MMA GEMM.
// Block: 512 thr, 128 nodes. Out = [128 nodes x 256 ch] = [A | B] rows.
// smem: XHI/XLO [128][272], WHI/WLO [256][272]
// ---------------------------------------------------------------------------
#define PC_XHI  0
#define PC_XLO  34816
#define PC_WHI  69632
#define PC_WLO  139264
#define PC_SMEM 208896

__global__ void __launch_bounds__(512, 1)
precompute_mma_kernel(const float* __restrict__ x, const float* __restrict__ W1, int N)
{
    extern __shared__ __align__(128) char smc[];
    u32 sb = smem_u32(smc);
    int tid = threadIdx.x;
    int lane = tid & 31, w = tid >> 5;
    int n0 = blockIdx.x * 128;

    // Stage W1 rearranged: row j<128 -> W1[j][0:128]; j>=128 -> W1[j-128][128:256]
    const float4* W1v = (const float4*)W1;
    for (int idx = tid; idx < 256 * 32; idx += 512) {
        int j = idx >> 5, c4 = idx & 31;
        float4 v = (j < 128) ? W1v[j * 64 + c4] : W1v[(j - 128) * 64 + 32 + c4];
        ull hp, lp;
        split4(v, hp, lp);
        *(ull*)(smc + PC_WHI + j * HSTRIDE + c4 * 8) = hp;
        *(ull*)(smc + PC_WLO + j * HSTRIDE + c4 * 8) = lp;
    }
    // Stage x tile (clamped rows)
    for (int idx = tid; idx < 128 * 32; idx += 512) {
        int r = idx >> 5, c4 = idx & 31;
        int n = min(n0 + r, N - 1);
        float4 v = ((const float4*)x)[(size_t)n * 32 + c4];
        ull hp, lp;
        split4(v, hp, lp);
        *(ull*)(smc + PC_XHI + r * HSTRIDE + c4 * 8) = hp;
        *(ull*)(smc + PC_XLO + r * HSTRIDE + c4 * 8) = lp;
    }
    __syncthreads();

    // Warp tile: rows [wm*32,+32), cols [wn*64,+64) of 256
    int wm = w & 3, wn = w >> 2;
    int g = lane >> 3, lr = lane & 7;
    int arow = (g & 1) * 8 + lr;
    u32 kh = (u32)((g >> 1) * 16);

    u32 aBaseHi = sb + PC_XHI + (wm * 32 + arow) * HSTRIDE + kh;
    u32 aBaseLo = sb + PC_XLO + (wm * 32 + arow) * HSTRIDE + kh;
    u32 bBaseHi = sb + PC_WHI + (wn * 64 + arow) * HSTRIDE + kh;
    u32 bBaseLo = sb + PC_WLO + (wn * 64 + arow) * HSTRIDE + kh;

    float acc[2][8][4];
    #pragma unroll
    for (int mi = 0; mi < 2; mi++)
        #pragma unroll
        for (int ni = 0; ni < 8; ni++)
            #pragma unroll
            for (int q = 0; q < 4; q++) acc[mi][ni][q] = 0.0f;

    #pragma unroll
    for (int ks = 0; ks < 8; ks++) {
        u32 ko = (u32)(ks * 32);
        u32 bh[8][2], bl[8][2];
        #pragma unroll
        for (int gB = 0; gB < 4; gB++) {
            u32 r0,r1,r2,r3;
            ldsm4(r0,r1,r2,r3, bBaseHi + gB * 16 * HSTRIDE + ko);
            bh[gB*2][0]=r0; bh[gB*2][1]=r2; bh[gB*2+1][0]=r1; bh[gB*2+1][1]=r3;
        }
        #pragma unroll
        for (int gB = 0; gB < 4; gB++) {
            u32 r0,r1,r2,r3;
            ldsm4(r0,r1,r2,r3, bBaseLo + gB * 16 * HSTRIDE + ko);
            bl[gB*2][0]=r0; bl[gB*2][1]=r2; bl[gB*2+1][0]=r1; bl[gB*2+1][1]=r3;
        }
        #pragma unroll
        for (int mi = 0; mi < 2; mi++) {
            u32 a0,a1,a2,a3, c0,c1,c2,c3;
            ldsm4(a0,a1,a2,a3, aBaseHi + mi * 16 * HSTRIDE + ko);
            ldsm4(c0,c1,c2,c3, aBaseLo + mi * 16 * HSTRIDE + ko);
            #pragma unroll
            for (int ni = 0; ni < 8; ni++) {
                mma_bf16(acc[mi][ni], a0,a1,a2,a3, bh[ni][0], bh[ni][1]);
                mma_bf16(acc[mi][ni], a0,a1,a2,a3, bl[ni][0], bl[ni][1]);
                mma_bf16(acc[mi][ni], c0,c1,c2,c3, bh[ni][0], bh[ni][1]);
            }
        }
    }

    // Epilogue: write fp32 results to g_A (wn<2) or g_B (wn>=2)
    float* dst = (wn < 2) ? g_A : g_B;
    int jbase = (wn & 1) * 64;
    #pragma unroll
    for (int mi = 0; mi < 2; mi++) {
        int r0 = wm * 32 + mi * 16 + (lane >> 2);
        #pragma unroll
        for (int ni = 0; ni < 8; ni++) {
            int j = jbase + ni * 8 + (lane & 3) * 2;
            int n_a = n0 + r0, n_b = n0 + r0 + 8;
            if (n_a < N) *(float2*)&dst[(size_t)n_a * C + j] = make_float2(acc[mi][ni][0], acc[mi][ni][1]);
            if (n_b < N) *(float2*)&dst[(size_t)n_b * C + j] = make_float2(acc[mi][ni][2], acc[mi][ni][3]);
        }
    }
}

// ---------------------------------------------------------------------------
// Kernel 2: warp-specialized pipelined edge MLP.
// ---------------------------------------------------------------------------
#define HTILE   (ET * HSTRIDE)            // 34816
#define OFF_WHI  0
#define OFF_WLO  34816
#define OFF_H    69632                    // buf b: HHI @ +b*2*HTILE, HLO @ +HTILE
#define OFF_B1   208896
#define OFF_B2   209408
#define OFF_W3   209920
#define OFF_PART 210432                   // [2 parity][2 wh][128] f32
#define OFF_B3   212480
#define ED_SMEM  212608

#define NTILES(E) (((E) + ET - 1) / ET)

__global__ void __launch_bounds__(512, 1)
edge_kernel(const void* __restrict__ ei,
            const float* __restrict__ W2, const float* __restrict__ b1,
            const float* __restrict__ b2, const float* __restrict__ W3,
            const float* __restrict__ b3, float* __restrict__ out, int E)
{
    extern __shared__ __align__(128) char smc[];
    u32 sb = smem_u32(smc);
    float* b1s = (float*)(smc + OFF_B1);
    float* b2s = (float*)(smc + OFF_B2);
    float* w3s = (float*)(smc + OFF_W3);
    float* part = (float*)(smc + OFF_PART);

    int tid = threadIdx.x;
    int lane = tid & 31, w = tid >> 5;
    bool i64 = idx_is_i64(ei);

    if (tid < 128) { b1s[tid] = b1[tid]; b2s[tid] = b2[tid]; w3s[tid] = W3[tid]; }
    if (tid == 0) *(float*)(smc + OFF_B3) = b3[0];
    const float4* W2v = (const float4*)W2;
    for (int idx = tid; idx < 128 * 32; idx += 512) {
        int j = idx >> 5, c4 = idx & 31;
        ull hp, lp;
        split4(W2v[idx], hp, lp);
        *(ull*)(smc + OFF_WHI + j * HSTRIDE + c4 * 8) = hp;
        *(ull*)(smc + OFF_WLO + j * HSTRIDE + c4 * 8) = lp;
    }
    __syncthreads();

    int ntiles = NTILES(E);

    if (w < 8) {
        // ========== PRODUCERS (256 thr): 8 lanes per edge, line-coalesced ==========
        int el0 = w * 16;                  // 16 edges per producer warp
        int r = lane >> 3;                 // edge-in-group 0..3
        int q = lane & 7;                  // float4 index within 128B line
        const float4* b1v = (const float4*)b1s;
        int i = 0;
        for (int t = blockIdx.x; t < ntiles; t += EDGE_GRID, i++) {
            int b = i & 1;
            // lanes 0-15: src idx of edge el0+lane; lanes 16-31: tgt idx
            int myidx;
            {
                int ee = min(t * ET + el0 + (lane & 15), E - 1);
                if (i64) {
                    const long long* qq = (const long long*)ei;
                    myidx = (int)((lane < 16) ? qq[ee] : qq[(size_t)E + ee]);
                } else {
                    const int* qq = (const int*)ei;
                    myidx = (lane < 16) ? qq[ee] : qq[(size_t)E + ee];
                }
            }
            if (i >= NBUF) BAR_SYNC(3 + b, 512);
            #pragma unroll
            for (int gg = 0; gg < 4; gg++) {
                int j = gg * 4 + r;
                int s  = __shfl_sync(0xFFFFFFFFu, myidx, j);
                int tg = __shfl_sync(0xFFFFFFFFu, myidx, 16 + j);
                const float4* Ar = (const float4*)g_A + (size_t)s  * 32 + q;
                const float4* Br = (const float4*)g_B + (size_t)tg * 32 + q;
                float4 av[4], bv[4];
                #pragma unroll
                for (int p = 0; p < 4; p++) { av[p] = Ar[8 * p]; bv[p] = Br[8 * p]; }
                char* hh = smc + OFF_H + b * 2 * HTILE + (el0 + j) * HSTRIDE + q * 8;
                #pragma unroll
                for (int p = 0; p < 4; p++) {
                    float4 bi = b1v[q + 8 * p];
                    float4 h;
                    h.x = elu_fast(av[p].x + bv[p].x + bi.x);
                    h.y = elu_fast(av[p].y + bv[p].y + bi.y);
                    h.z = elu_fast(av[p].z + bv[p].z + bi.z);
                    h.w = elu_fast(av[p].w + bv[p].w + bi.w);
                    ull hp, lp;
                    split4(h, hp, lp);
                    *(ull*)(hh + p * 64)         = hp;
                    *(ull*)(hh + p * 64 + HTILE) = lp;
                }
            }
            MEMBAR_CTA();
            BAR_ARRIVE(1 + b, 512);
        }
    } else {
        // ========== CONSUMERS (256 thr) ==========
        int cw = w - 8;
        int wm = cw & 3;                  // row block [wm*32,+32)
        int wh = cw >> 2;                 // col half  [wh*64,+64)
        int g  = lane >> 3, lr = lane & 7;
        int arow = (g & 1) * 8 + lr;
        u32 kh = (u32)((g >> 1) * 16);

        u32 bBaseHi = sb + OFF_WHI + (wh * 64 + arow) * HSTRIDE + kh;
        u32 bBaseLo = sb + OFF_WLO + (wh * 64 + arow) * HSTRIDE + kh;

        float b3v = *(float*)(smc + OFF_B3);
        int i = 0;
        for (int t = blockIdx.x; t < ntiles; t += EDGE_GRID, i++) {
            int b = i & 1;
            BAR_SYNC(1 + b, 512);

            u32 aBaseHi = sb + OFF_H + b * 2 * HTILE + (wm * 32 + arow) * HSTRIDE + kh;
            u32 aBaseLo = aBaseHi + (u32)HTILE;

            float acc[2][8][4];
            #pragma unroll
            for (int mi = 0; mi < 2; mi++)
                #pragma unroll
                for (int ni = 0; ni < 8; ni++)
                    #pragma unroll
                    for (int q = 0; q < 4; q++) acc[mi][ni][q] = 0.0f;

            #pragma unroll
            for (int ks = 0; ks < 8; ks++) {
                u32 ko = (u32)(ks * 32);
                u32 bh[8][2], bl[8][2];
                #pragma unroll
                for (int gB = 0; gB < 4; gB++) {
                    u32 r0,r1,r2,r3;
                    ldsm4(r0,r1,r2,r3, bBaseHi + gB * 16 * HSTRIDE + ko);
                    bh[gB*2][0]=r0; bh[gB*2][1]=r2; bh[gB*2+1][0]=r1; bh[gB*2+1][1]=r3;
                }
                #pragma unroll
                for (int gB = 0; gB < 4; gB++) {
                    u32 r0,r1,r2,r3;
                    ldsm4(r0,r1,r2,r3, bBaseLo + gB * 16 * HSTRIDE + ko);
                    bl[gB*2][0]=r0; bl[gB*2][1]=r2; bl[gB*2+1][0]=r1; bl[gB*2+1][1]=r3;
                }
                #pragma unroll
                for (int mi = 0; mi < 2; mi++) {
                    u32 a0,a1,a2,a3, c0,c1,c2,c3;
                    ldsm4(a0,a1,a2,a3, aBaseHi + mi * 16 * HSTRIDE + ko);
                    ldsm4(c0,c1,c2,c3, aBaseLo + mi * 16 * HSTRIDE + ko);
                    #pragma unroll
                    for (int ni = 0; ni < 8; ni++) {
                        mma_bf16(acc[mi][ni], a0,a1,a2,a3, bh[ni][0], bh[ni][1]);
                        mma_bf16(acc[mi][ni], a0,a1,a2,a3, bl[ni][0], bl[ni][1]);
                        mma_bf16(acc[mi][ni], c0,c1,c2,c3, bh[ni][0], bh[ni][1]);
                    }
                }
            }
            BAR_ARRIVE(3 + b, 512);        // buffer free; epilogue in regs only

            int par = i & 1;
            float* pp = part + par * 256 + wh * 128;
            #pragma unroll
            for (int mi = 0; mi < 2; mi++) {
                float p0 = 0.0f, p1 = 0.0f;
                #pragma unroll
                for (int ni = 0; ni < 8; ni++) {
                    int j = wh * 64 + ni * 8 + (lane & 3) * 2;
                    float w3a = w3s[j], w3b = w3s[j + 1];
                    float b2a = b2s[j], b2b = b2s[j + 1];
                    p0 = fmaf(w3a, elu_fast(acc[mi][ni][0] + b2a), p0);
                    p0 = fmaf(w3b, elu_fast(acc[mi][ni][1] + b2b), p0);
                    p1 = fmaf(w3a, elu_fast(acc[mi][ni][2] + b2a), p1);
                    p1 = fmaf(w3b, elu_fast(acc[mi][ni][3] + b2b), p1);
                }
                p0 += __shfl_xor_sync(0xFFFFFFFFu, p0, 1);
                p0 += __shfl_xor_sync(0xFFFFFFFFu, p0, 2);
                p1 += __shfl_xor_sync(0xFFFFFFFFu, p1, 1);
                p1 += __shfl_xor_sync(0xFFFFFFFFu, p1, 2);
                if ((lane & 3) == 0) {
                    int r = wm * 32 + mi * 16 + (lane >> 2);
                    pp[r]     = p0;
                    pp[r + 8] = p1;
                }
            }
            BAR_SYNC(5, 256);               // consumer-only
            int ctid = tid - 256;
            if (ctid < 128) {
                int e = t * ET + ctid;
                if (e < E)
                    out[e] = part[par * 256 + ctid] + part[par * 256 + 128 + ctid] + b3v;
            }
        }
    }
}

// ---------------------------------------------------------------------------
extern "C" void kernel_launch(void* const* d_in, const int* in_sizes, int n_in,
                              void* d_out, int out_size)
{
    const float* x  = (const float*)d_in[0];
    const void*  ei = d_in[1];
    const float* W1 = (const float*)d_in[2];
    const float* b1 = (const float*)d_in[3];
    const float* W2 = (const float*)d_in[4];
    const float* b2 = (const float*)d_in[5];
    const float* W3 = (const float*)d_in[6];
    const float* b3 = (const float*)d_in[7];
    float* out = (float*)d_out;

    int N = in_sizes[0] / C;        // 50000
    int E = in_sizes[1] / 2;        // 640000

    cudaFuncSetAttribute(precompute_mma_kernel, cudaFuncAttributeMaxDynamicSharedMemorySize, PC_SMEM);
    cudaFuncSetAttribute(edge_kernel,           cudaFuncAttributeMaxDynamicSharedMemorySize, ED_SMEM);

    precompute_mma_kernel<<<(N + 127) / 128, 512, PC_SMEM>>>(x, W1, N);
    edge_kernel<<<EDGE_GRID, 512, ED_SMEM>>>(ei, W2, b1, b2, W3, b3, out, E);
}

// round 9
// speedup vs baseline: 3.3351x; 1.2337x over previous
#include <cuda_runtime.h>
#include <cuda_bf16.h>
#include <cstdint>

// EdgeMLPMPN: out[e] = W3 @ elu(W2 @ elu(W1 @ [x[src];x[tgt]] + b1) + b2) + b3
//   Kernel 1 (split-bf16 mma.sync GEMM, proven): [A|B](n) = [W1a|W1b] @ x[n]
//   Kernel 2 (warp-specialized pipeline, TF32 single-pass):
//       producers (warps 0-7): line-coalesced gather + elu + cvt.rna.tf32 -> 2-buffered H tiles
//       consumers (warps 8-15): single-pass m16n8k8 tf32 mma + fused epilogue
// Compiled at sm_100 (no 'a'): mma.sync only, no tcgen05.

#define C 128
#define NMAX 50000
#define ET 128
#define NBUF 2
#define EDGE_GRID 296
typedef unsigned long long ull;
typedef uint32_t u32;

__device__ float g_A[(size_t)NMAX * C];
__device__ float g_B[(size_t)NMAX * C];

__device__ __forceinline__ float elu_fast(float x) {
    return x > 0.0f ? x : (__expf(x) - 1.0f);
}

__device__ __forceinline__ bool idx_is_i64(const void* p) {
    const ull* q = (const ull*)p;
    unsigned hi = 0;
    #pragma unroll
    for (int i = 0; i < 8; i++) hi |= (unsigned)(q[i] >> 32);
    return hi == 0;
}

__device__ __forceinline__ u32 smem_u32(const void* p) {
    u32 a; asm("{ .reg .u64 t; cvta.to.shared.u64 t, %1; cvt.u32.u64 %0, t; }" : "=r"(a) : "l"(p));
    return a;
}

__device__ __forceinline__ void ldsm4(u32 &r0, u32 &r1, u32 &r2, u32 &r3, u32 addr) {
    asm volatile("ldmatrix.sync.aligned.m8n8.x4.shared.b16 {%0,%1,%2,%3}, [%4];"
                 : "=r"(r0), "=r"(r1), "=r"(r2), "=r"(r3) : "r"(addr));
}

__device__ __forceinline__ void mma_bf16(float* d, u32 a0, u32 a1, u32 a2, u32 a3,
                                         u32 b0, u32 b1) {
    asm volatile("mma.sync.aligned.m16n8k16.row.col.f32.bf16.bf16.f32 "
                 "{%0,%1,%2,%3}, {%4,%5,%6,%7}, {%8,%9}, {%0,%1,%2,%3};"
                 : "+f"(d[0]), "+f"(d[1]), "+f"(d[2]), "+f"(d[3])
                 : "r"(a0), "r"(a1), "r"(a2), "r"(a3), "r"(b0), "r"(b1));
}

__device__ __forceinline__ void mma_tf32(float* d, u32 a0, u32 a1, u32 a2, u32 a3,
                                         u32 b0, u32 b1) {
    asm volatile("mma.sync.aligned.m16n8k8.row.col.f32.tf32.tf32.f32 "
                 "{%0,%1,%2,%3}, {%4,%5,%6,%7}, {%8,%9}, {%0,%1,%2,%3};"
                 : "+f"(d[0]), "+f"(d[1]), "+f"(d[2]), "+f"(d[3])
                 : "r"(a0), "r"(a1), "r"(a2), "r"(a3), "r"(b0), "r"(b1));
}

__device__ __forceinline__ u32 cvt_tf32(float f) {
    u32 r; asm("cvt.rna.tf32.f32 %0, %1;" : "=r"(r) : "f"(f));
    return r;
}

__device__ __forceinline__ u32 cvt_bf2(float lo, float hi) {
    u32 r; asm("cvt.rn.bf16x2.f32 %0, %1, %2;" : "=r"(r) : "f"(hi), "f"(lo));
    return r;
}

__device__ __forceinline__ void split4(float4 h, ull &hiP, ull &loP) {
    u32 hxy = cvt_bf2(h.x, h.y);
    u32 hzw = cvt_bf2(h.z, h.w);
    float rx = h.x - __uint_as_float(hxy << 16);
    float ry = h.y - __uint_as_float(hxy & 0xFFFF0000u);
    float rz = h.z - __uint_as_float(hzw << 16);
    float rw = h.w - __uint_as_float(hzw & 0xFFFF0000u);
    u32 lxy = cvt_bf2(rx, ry);
    u32 lzw = cvt_bf2(rz, rw);
    hiP = (ull)hxy | ((ull)hzw << 32);
    loP = (ull)lxy | ((ull)lzw << 32);
}

#define BAR_SYNC(id, n)   asm volatile("bar.sync %0, %1;"   :: "r"(id), "r"(n) : "memory")
#define BAR_ARRIVE(id, n) asm volatile("bar.arrive %0, %1;" :: "r"(id), "r"(n) : "memory")
#define MEMBAR_CTA()      asm volatile("membar.cta;" ::: "memory")

#define HSTRIDE 272

// ---------------------------------------------------------------------------
// Kernel 1: node precompute as split-bf16 MMA GEMM (unchanged, proven).
// ---------------------------------------------------------------------------
#define PC_XHI  0
#define PC_XLO  34816
#define PC_WHI  69632
#define PC_WLO  139264
#define PC_SMEM 208896

__global__ void __launch_bounds__(512, 1)
precompute_mma_kernel(const float* __restrict__ x, const float* __restrict__ W1, int N)
{
    extern __shared__ __align__(128) char smc[];
    u32 sb = smem_u32(smc);
    int tid = threadIdx.x;
    int lane = tid & 31, w = tid >> 5;
    int n0 = blockIdx.x * 128;

    const float4* W1v = (const float4*)W1;
    for (int idx = tid; idx < 256 * 32; idx += 512) {
        int j = idx >> 5, c4 = idx & 31;
        float4 v = (j < 128) ? W1v[j * 64 + c4] : W1v[(j - 128) * 64 + 32 + c4];
        ull hp, lp;
        split4(v, hp, lp);
        *(ull*)(smc + PC_WHI + j * HSTRIDE + c4 * 8) = hp;
        *(ull*)(smc + PC_WLO + j * HSTRIDE + c4 * 8) = lp;
    }
    for (int idx = tid; idx < 128 * 32; idx += 512) {
        int r = idx >> 5, c4 = idx & 31;
        int n = min(n0 + r, N - 1);
        float4 v = ((const float4*)x)[(size_t)n * 32 + c4];
        ull hp, lp;
        split4(v, hp, lp);
        *(ull*)(smc + PC_XHI + r * HSTRIDE + c4 * 8) = hp;
        *(ull*)(smc + PC_XLO + r * HSTRIDE + c4 * 8) = lp;
    }
    __syncthreads();

    int wm = w & 3, wn = w >> 2;
    int g = lane >> 3, lr = lane & 7;
    int arow = (g & 1) * 8 + lr;
    u32 kh = (u32)((g >> 1) * 16);

    u32 aBaseHi = sb + PC_XHI + (wm * 32 + arow) * HSTRIDE + kh;
    u32 aBaseLo = sb + PC_XLO + (wm * 32 + arow) * HSTRIDE + kh;
    u32 bBaseHi = sb + PC_WHI + (wn * 64 + arow) * HSTRIDE + kh;
    u32 bBaseLo = sb + PC_WLO + (wn * 64 + arow) * HSTRIDE + kh;

    float acc[2][8][4];
    #pragma unroll
    for (int mi = 0; mi < 2; mi++)
        #pragma unroll
        for (int ni = 0; ni < 8; ni++)
            #pragma unroll
            for (int q = 0; q < 4; q++) acc[mi][ni][q] = 0.0f;

    #pragma unroll
    for (int ks = 0; ks < 8; ks++) {
        u32 ko = (u32)(ks * 32);
        u32 bh[8][2], bl[8][2];
        #pragma unroll
        for (int gB = 0; gB < 4; gB++) {
            u32 r0,r1,r2,r3;
            ldsm4(r0,r1,r2,r3, bBaseHi + gB * 16 * HSTRIDE + ko);
            bh[gB*2][0]=r0; bh[gB*2][1]=r2; bh[gB*2+1][0]=r1; bh[gB*2+1][1]=r3;
        }
        #pragma unroll
        for (int gB = 0; gB < 4; gB++) {
            u32 r0,r1,r2,r3;
            ldsm4(r0,r1,r2,r3, bBaseLo + gB * 16 * HSTRIDE + ko);
            bl[gB*2][0]=r0; bl[gB*2][1]=r2; bl[gB*2+1][0]=r1; bl[gB*2+1][1]=r3;
        }
        #pragma unroll
        for (int mi = 0; mi < 2; mi++) {
            u32 a0,a1,a2,a3, c0,c1,c2,c3;
            ldsm4(a0,a1,a2,a3, aBaseHi + mi * 16 * HSTRIDE + ko);
            ldsm4(c0,c1,c2,c3, aBaseLo + mi * 16 * HSTRIDE + ko);
            #pragma unroll
            for (int ni = 0; ni < 8; ni++) {
                mma_bf16(acc[mi][ni], a0,a1,a2,a3, bh[ni][0], bh[ni][1]);
                mma_bf16(acc[mi][ni], a0,a1,a2,a3, bl[ni][0], bl[ni][1]);
                mma_bf16(acc[mi][ni], c0,c1,c2,c3, bh[ni][0], bh[ni][1]);
            }
        }
    }

    float* dst = (wn < 2) ? g_A : g_B;
    int jbase = (wn & 1) * 64;
    #pragma unroll
    for (int mi = 0; mi < 2; mi++) {
        int r0 = wm * 32 + mi * 16 + (lane >> 2);
        #pragma unroll
        for (int ni = 0; ni < 8; ni++) {
            int j = jbase + ni * 8 + (lane & 3) * 2;
            int n_a = n0 + r0, n_b = n0 + r0 + 8;
            if (n_a < N) *(float2*)&dst[(size_t)n_a * C + j] = make_float2(acc[mi][ni][0], acc[mi][ni][1]);
            if (n_b < N) *(float2*)&dst[(size_t)n_b * C + j] = make_float2(acc[mi][ni][2], acc[mi][ni][3]);
        }
    }
}

// ---------------------------------------------------------------------------
// Kernel 2: warp-specialized pipelined edge MLP, TF32 single-pass.
// smem:
//   WP  [128 n][16 ks][4 q][2] f32 pairs (W[n][8ks+q], W[n][8ks+q+4]), stride 544B
//   H   2 buffers x [128 e][132 f32] (stride 528B), tf32 bit patterns
// ---------------------------------------------------------------------------
#define WP_STRIDE 544
#define H_STRIDE  528
#define H_TILE    (ET * H_STRIDE)          // 67584
#define OFF_WP    0                        // 69632
#define OFF_H     69632                    // + 2*67584 = 204800
#define OFF_B1    204800
#define OFF_B2    205312
#define OFF_W3    205824
#define OFF_PART  206336                   // 2048
#define OFF_B3    208384
#define ED_SMEM   208512

#define NTILES(E) (((E) + ET - 1) / ET)

__global__ void __launch_bounds__(512, 1)
edge_kernel(const void* __restrict__ ei,
            const float* __restrict__ W2, const float* __restrict__ b1,
            const float* __restrict__ b2, const float* __restrict__ W3,
            const float* __restrict__ b3, float* __restrict__ out, int E)
{
    extern __shared__ __align__(128) char smc[];
    u32 sb = smem_u32(smc);
    float* b1s = (float*)(smc + OFF_B1);
    float* b2s = (float*)(smc + OFF_B2);
    float* w3s = (float*)(smc + OFF_W3);
    float* part = (float*)(smc + OFF_PART);

    int tid = threadIdx.x;
    int lane = tid & 31, w = tid >> 5;
    bool i64 = idx_is_i64(ei);

    if (tid < 128) { b1s[tid] = b1[tid]; b2s[tid] = b2[tid]; w3s[tid] = W3[tid]; }
    if (tid == 0) *(float*)(smc + OFF_B3) = b3[0];
    // Stage W2 into paired tf32 layout (rna-rounded): slot (n, ks, q) <- (W[n][8ks+q], W[n][8ks+q+4])
    for (int idx = tid; idx < 128 * 64; idx += 512) {
        int n = idx >> 6, rest = idx & 63;
        int ks = rest >> 2, q = rest & 3;
        u32 v0 = cvt_tf32(W2[n * 128 + ks * 8 + q]);
        u32 v1 = cvt_tf32(W2[n * 128 + ks * 8 + q + 4]);
        *(ull*)(smc + OFF_WP + n * WP_STRIDE + ks * 32 + q * 8) = (ull)v0 | ((ull)v1 << 32);
    }
    __syncthreads();

    int ntiles = NTILES(E);

    if (w < 8) {
        // ========== PRODUCERS (256 thr): 8 lanes per edge, line-coalesced ==========
        int el0 = w * 16;                  // 16 edges per producer warp
        int r = lane >> 3;                 // edge-in-group 0..3
        int q = lane & 7;                  // float4 index within 128B line
        const float4* b1v = (const float4*)b1s;
        int i = 0;
        for (int t = blockIdx.x; t < ntiles; t += EDGE_GRID, i++) {
            int b = i & 1;
            int myidx;
            {
                int ee = min(t * ET + el0 + (lane & 15), E - 1);
                if (i64) {
                    const long long* qq = (const long long*)ei;
                    myidx = (int)((lane < 16) ? qq[ee] : qq[(size_t)E + ee]);
                } else {
                    const int* qq = (const int*)ei;
                    myidx = (lane < 16) ? qq[ee] : qq[(size_t)E + ee];
                }
            }
            if (i >= NBUF) BAR_SYNC(3 + b, 512);
            #pragma unroll
            for (int gg = 0; gg < 4; gg++) {
                int j = gg * 4 + r;
                int s  = __shfl_sync(0xFFFFFFFFu, myidx, j);
                int tg = __shfl_sync(0xFFFFFFFFu, myidx, 16 + j);
                const float4* Ar = (const float4*)g_A + (size_t)s  * 32 + q;
                const float4* Br = (const float4*)g_B + (size_t)tg * 32 + q;
                float4 av[4], bv[4];
                #pragma unroll
                for (int p = 0; p < 4; p++) { av[p] = Ar[8 * p]; bv[p] = Br[8 * p]; }
                char* hh = smc + OFF_H + b * H_TILE + (el0 + j) * H_STRIDE + q * 16;
                #pragma unroll
                for (int p = 0; p < 4; p++) {
                    float4 bi = b1v[q + 8 * p];
                    uint4 hv;
                    hv.x = cvt_tf32(elu_fast(av[p].x + bv[p].x + bi.x));
                    hv.y = cvt_tf32(elu_fast(av[p].y + bv[p].y + bi.y));
                    hv.z = cvt_tf32(elu_fast(av[p].z + bv[p].z + bi.z));
                    hv.w = cvt_tf32(elu_fast(av[p].w + bv[p].w + bi.w));
                    *(uint4*)(hh + p * 128) = hv;   // channels 32p..32p+3 block: q*16 + p*128 bytes
                }
            }
            MEMBAR_CTA();
            BAR_ARRIVE(1 + b, 512);
        }
    } else {
        // ========== CONSUMERS (256 thr): single-pass tf32 ==========
        int cw = w - 8;
        int wm = cw & 3;                  // row block [wm*32,+32)
        int wh = cw >> 2;                 // col half  [wh*64,+64)
        int lg = lane >> 2;               // group id 0..7
        int lq = lane & 3;                // thread-in-group

        // B base: row n = wh*64 + ni*8 + lg, pair q = lq
        u32 bBase = sb + OFF_WP + (wh * 64 + lg) * WP_STRIDE + lq * 8;

        float b3v = *(float*)(smc + OFF_B3);
        int i = 0;
        for (int t = blockIdx.x; t < ntiles; t += EDGE_GRID, i++) {
            int b = i & 1;
            BAR_SYNC(1 + b, 512);

            // A base: row = wm*32 + mi*16 + lg (+8), col = ks*8 + lq (+4)
            u32 aBase = sb + OFF_H + b * H_TILE + (wm * 32 + lg) * H_STRIDE + lq * 4;

            float acc[2][8][4];
            #pragma unroll
            for (int mi = 0; mi < 2; mi++)
                #pragma unroll
                for (int ni = 0; ni < 8; ni++)
                    #pragma unroll
                    for (int qq = 0; qq < 4; qq++) acc[mi][ni][qq] = 0.0f;

            #pragma unroll
            for (int ks = 0; ks < 16; ks++) {
                u32 ko = (u32)(ks * 32);
                u32 bb[8][2];
                #pragma unroll
                for (int ni = 0; ni < 8; ni++) {
                    ull v = *(const ull*)(smc + (bBase - sb) + ni * 8 * WP_STRIDE + ko);
                    bb[ni][0] = (u32)v; bb[ni][1] = (u32)(v >> 32);
                }
                #pragma unroll
                for (int mi = 0; mi < 2; mi++) {
                    u32 ab = aBase - sb + mi * 16 * H_STRIDE + ko;
                    u32 a0 = *(const u32*)(smc + ab);
                    u32 a2 = *(const u32*)(smc + ab + 16);
                    u32 a1 = *(const u32*)(smc + ab + 8 * H_STRIDE);
                    u32 a3 = *(const u32*)(smc + ab + 8 * H_STRIDE + 16);
                    #pragma unroll
                    for (int ni = 0; ni < 8; ni++)
                        mma_tf32(acc[mi][ni], a0, a1, a2, a3, bb[ni][0], bb[ni][1]);
                }
            }
            BAR_ARRIVE(3 + b, 512);        // buffer free; epilogue in regs only

            int par = i & 1;
            float* pp = part + par * 256 + wh * 128;
            #pragma unroll
            for (int mi = 0; mi < 2; mi++) {
                float p0 = 0.0f, p1 = 0.0f;
                #pragma unroll
                for (int ni = 0; ni < 8; ni++) {
                    int j = wh * 64 + ni * 8 + lq * 2;
                    float w3a = w3s[j], w3b = w3s[j + 1];
                    float b2a = b2s[j], b2b = b2s[j + 1];
                    p0 = fmaf(w3a, elu_fast(acc[mi][ni][0] + b2a), p0);
                    p0 = fmaf(w3b, elu_fast(acc[mi][ni][1] + b2b), p0);
                    p1 = fmaf(w3a, elu_fast(acc[mi][ni][2] + b2a), p1);
                    p1 = fmaf(w3b, elu_fast(acc[mi][ni][3] + b2b), p1);
                }
                p0 += __shfl_xor_sync(0xFFFFFFFFu, p0, 1);
                p0 += __shfl_xor_sync(0xFFFFFFFFu, p0, 2);
                p1 += __shfl_xor_sync(0xFFFFFFFFu, p1, 1);
                p1 += __shfl_xor_sync(0xFFFFFFFFu, p1, 2);
                if (lq == 0) {
                    int rr = wm * 32 + mi * 16 + lg;
                    pp[rr]     = p0;
                    pp[rr + 8] = p1;
                }
            }
            BAR_SYNC(5, 256);               // consumer-only
            int ctid = tid - 256;
            if (ctid < 128) {
                int e = t * ET + ctid;
                if (e < E)
                    out[e] = part[par * 256 + ctid] + part[par * 256 + 128 + ctid] + b3v;
            }
        }
    }
}

// ---------------------------------------------------------------------------
extern "C" void kernel_launch(void* const* d_in, const int* in_sizes, int n_in,
                              void* d_out, int out_size)
{
    const float* x  = (const float*)d_in[0];
    const void*  ei = d_in[1];
    const float* W1 = (const float*)d_in[2];
    const float* b1 = (const float*)d_in[3];
    const float* W2 = (const float*)d_in[4];
    const float* b2 = (const float*)d_in[5];
    const float* W3 = (const float*)d_in[6];
    const float* b3 = (const float*)d_in[7];
    float* out = (float*)d_out;

    int N = in_sizes[0] / C;        // 50000
    int E = in_sizes[1] / 2;        // 640000

    cudaFuncSetAttribute(precompute_mma_kernel, cudaFuncAttributeMaxDynamicSharedMemorySize, PC_SMEM);
    cudaFuncSetAttribute(edge_kernel,           cudaFuncAttributeMaxDynamicSharedMemorySize, ED_SMEM);

    precompute_mma_kernel<<<(N + 127) / 128, 512, PC_SMEM>>>(x, W1, N);
    edge_kernel<<<EDGE_GRID, 512, ED_SMEM>>>(ei, W2, b1, b2, W3, b3, out, E);
}

// round 10
// speedup vs baseline: 3.8401x; 1.1514x over previous
#include <cuda_runtime.h>
#include <cuda_bf16.h>
#include <cstdint>

// EdgeMLPMPN: out[e] = W3 @ elu(W2 @ elu(W1 @ [x[src];x[tgt]] + b1) + b2) + b3
//   Kernel 1 (split-bf16 mma.sync GEMM, proven): [A|B](n) = [W1a|W1b] @ x[n]
//   Kernel 2 (warp-specialized pipeline, TF32 single-pass):
//       producers (warps 0-7): prefetch-pipelined gather + elu + cvt.rna.tf32
//       consumers (warps 8-15): single-pass m16n8k8 tf32 mma + pairwise epilogue
// Compiled at sm_100 (no 'a'): mma.sync only, no tcgen05.

#define C 128
#define NMAX 50000
#define ET 128
#define NBUF 2
#define EDGE_GRID 148
typedef unsigned long long ull;
typedef uint32_t u32;

__device__ float g_A[(size_t)NMAX * C];
__device__ float g_B[(size_t)NMAX * C];

__device__ __forceinline__ float elu_fast(float x) {
    return x > 0.0f ? x : (__expf(x) - 1.0f);
}

__device__ __forceinline__ bool idx_is_i64(const void* p) {
    const ull* q = (const ull*)p;
    unsigned hi = 0;
    #pragma unroll
    for (int i = 0; i < 8; i++) hi |= (unsigned)(q[i] >> 32);
    return hi == 0;
}

__device__ __forceinline__ u32 smem_u32(const void* p) {
    u32 a; asm("{ .reg .u64 t; cvta.to.shared.u64 t, %1; cvt.u32.u64 %0, t; }" : "=r"(a) : "l"(p));
    return a;
}

__device__ __forceinline__ void ldsm4(u32 &r0, u32 &r1, u32 &r2, u32 &r3, u32 addr) {
    asm volatile("ldmatrix.sync.aligned.m8n8.x4.shared.b16 {%0,%1,%2,%3}, [%4];"
                 : "=r"(r0), "=r"(r1), "=r"(r2), "=r"(r3) : "r"(addr));
}

__device__ __forceinline__ void mma_bf16(float* d, u32 a0, u32 a1, u32 a2, u32 a3,
                                         u32 b0, u32 b1) {
    asm volatile("mma.sync.aligned.m16n8k16.row.col.f32.bf16.bf16.f32 "
                 "{%0,%1,%2,%3}, {%4,%5,%6,%7}, {%8,%9}, {%0,%1,%2,%3};"
                 : "+f"(d[0]), "+f"(d[1]), "+f"(d[2]), "+f"(d[3])
                 : "r"(a0), "r"(a1), "r"(a2), "r"(a3), "r"(b0), "r"(b1));
}

__device__ __forceinline__ void mma_tf32(float* d, u32 a0, u32 a1, u32 a2, u32 a3,
                                         u32 b0, u32 b1) {
    asm volatile("mma.sync.aligned.m16n8k8.row.col.f32.tf32.tf32.f32 "
                 "{%0,%1,%2,%3}, {%4,%5,%6,%7}, {%8,%9}, {%0,%1,%2,%3};"
                 : "+f"(d[0]), "+f"(d[1]), "+f"(d[2]), "+f"(d[3])
                 : "r"(a0), "r"(a1), "r"(a2), "r"(a3), "r"(b0), "r"(b1));
}

__device__ __forceinline__ u32 cvt_tf32(float f) {
    u32 r; asm("cvt.rna.tf32.f32 %0, %1;" : "=r"(r) : "f"(f));
    return r;
}

__device__ __forceinline__ u32 cvt_bf2(float lo, float hi) {
    u32 r; asm("cvt.rn.bf16x2.f32 %0, %1, %2;" : "=r"(r) : "f"(hi), "f"(lo));
    return r;
}

__device__ __forceinline__ void split4(float4 h, ull &hiP, ull &loP) {
    u32 hxy = cvt_bf2(h.x, h.y);
    u32 hzw = cvt_bf2(h.z, h.w);
    float rx = h.x - __uint_as_float(hxy << 16);
    float ry = h.y - __uint_as_float(hxy & 0xFFFF0000u);
    float rz = h.z - __uint_as_float(hzw << 16);
    float rw = h.w - __uint_as_float(hzw & 0xFFFF0000u);
    u32 lxy = cvt_bf2(rx, ry);
    u32 lzw = cvt_bf2(rz, rw);
    hiP = (ull)hxy | ((ull)hzw << 32);
    loP = (ull)lxy | ((ull)lzw << 32);
}

#define BAR_SYNC(id, n)   asm volatile("bar.sync %0, %1;"   :: "r"(id), "r"(n) : "memory")
#define BAR_ARRIVE(id, n) asm volatile("bar.arrive %0, %1;" :: "r"(id), "r"(n) : "memory")
#define MEMBAR_CTA()      asm volatile("membar.cta;" ::: "memory")

#define HSTRIDE 272

// ---------------------------------------------------------------------------
// Kernel 1: node precompute as split-bf16 MMA GEMM (unchanged, proven).
// ---------------------------------------------------------------------------
#define PC_XHI  0
#define PC_XLO  34816
#define PC_WHI  69632
#define PC_WLO  139264
#define PC_SMEM 208896

__global__ void __launch_bounds__(512, 1)
precompute_mma_kernel(const float* __restrict__ x, const float* __restrict__ W1, int N)
{
    extern __shared__ __align__(128) char smc[];
    u32 sb = smem_u32(smc);
    int tid = threadIdx.x;
    int lane = tid & 31, w = tid >> 5;
    int n0 = blockIdx.x * 128;

    const float4* W1v = (const float4*)W1;
    for (int idx = tid; idx < 256 * 32; idx += 512) {
        int j = idx >> 5, c4 = idx & 31;
        float4 v = (j < 128) ? W1v[j * 64 + c4] : W1v[(j - 128) * 64 + 32 + c4];
        ull hp, lp;
        split4(v, hp, lp);
        *(ull*)(smc + PC_WHI + j * HSTRIDE + c4 * 8) = hp;
        *(ull*)(smc + PC_WLO + j * HSTRIDE + c4 * 8) = lp;
    }
    for (int idx = tid; idx < 128 * 32; idx += 512) {
        int r = idx >> 5, c4 = idx & 31;
        int n = min(n0 + r, N - 1);
        float4 v = ((const float4*)x)[(size_t)n * 32 + c4];
        ull hp, lp;
        split4(v, hp, lp);
        *(ull*)(smc + PC_XHI + r * HSTRIDE + c4 * 8) = hp;
        *(ull*)(smc + PC_XLO + r * HSTRIDE + c4 * 8) = lp;
    }
    __syncthreads();

    int wm = w & 3, wn = w >> 2;
    int g = lane >> 3, lr = lane & 7;
    int arow = (g & 1) * 8 + lr;
    u32 kh = (u32)((g >> 1) * 16);

    u32 aBaseHi = sb + PC_XHI + (wm * 32 + arow) * HSTRIDE + kh;
    u32 aBaseLo = sb + PC_XLO + (wm * 32 + arow) * HSTRIDE + kh;
    u32 bBaseHi = sb + PC_WHI + (wn * 64 + arow) * HSTRIDE + kh;
    u32 bBaseLo = sb + PC_WLO + (wn * 64 + arow) * HSTRIDE + kh;

    float acc[2][8][4];
    #pragma unroll
    for (int mi = 0; mi < 2; mi++)
        #pragma unroll
        for (int ni = 0; ni < 8; ni++)
            #pragma unroll
            for (int q = 0; q < 4; q++) acc[mi][ni][q] = 0.0f;

    #pragma unroll
    for (int ks = 0; ks < 8; ks++) {
        u32 ko = (u32)(ks * 32);
        u32 bh[8][2], bl[8][2];
        #pragma unroll
        for (int gB = 0; gB < 4; gB++) {
            u32 r0,r1,r2,r3;
            ldsm4(r0,r1,r2,r3, bBaseHi + gB * 16 * HSTRIDE + ko);
            bh[gB*2][0]=r0; bh[gB*2][1]=r2; bh[gB*2+1][0]=r1; bh[gB*2+1][1]=r3;
        }
        #pragma unroll
        for (int gB = 0; gB < 4; gB++) {
            u32 r0,r1,r2,r3;
            ldsm4(r0,r1,r2,r3, bBaseLo + gB * 16 * HSTRIDE + ko);
            bl[gB*2][0]=r0; bl[gB*2][1]=r2; bl[gB*2+1][0]=r1; bl[gB*2+1][1]=r3;
        }
        #pragma unroll
        for (int mi = 0; mi < 2; mi++) {
            u32 a0,a1,a2,a3, c0,c1,c2,c3;
            ldsm4(a0,a1,a2,a3, aBaseHi + mi * 16 * HSTRIDE + ko);
            ldsm4(c0,c1,c2,c3, aBaseLo + mi * 16 * HSTRIDE + ko);
            #pragma unroll
            for (int ni = 0; ni < 8; ni++) {
                mma_bf16(acc[mi][ni], a0,a1,a2,a3, bh[ni][0], bh[ni][1]);
                mma_bf16(acc[mi][ni], a0,a1,a2,a3, bl[ni][0], bl[ni][1]);
                mma_bf16(acc[mi][ni], c0,c1,c2,c3, bh[ni][0], bh[ni][1]);
            }
        }
    }

    float* dst = (wn < 2) ? g_A : g_B;
    int jbase = (wn & 1) * 64;
    #pragma unroll
    for (int mi = 0; mi < 2; mi++) {
        int r0 = wm * 32 + mi * 16 + (lane >> 2);
        #pragma unroll
        for (int ni = 0; ni < 8; ni++) {
            int j = jbase + ni * 8 + (lane & 3) * 2;
            int n_a = n0 + r0, n_b = n0 + r0 + 8;
            if (n_a < N) *(float2*)&dst[(size_t)n_a * C + j] = make_float2(acc[mi][ni][0], acc[mi][ni][1]);
            if (n_b < N) *(float2*)&dst[(size_t)n_b * C + j] = make_float2(acc[mi][ni][2], acc[mi][ni][3]);
        }
    }
}

// ---------------------------------------------------------------------------
// Kernel 2: warp-specialized pipelined edge MLP, TF32 single-pass.
// ---------------------------------------------------------------------------
#define WP_STRIDE 544
#define H_STRIDE  528
#define H_TILE    (ET * H_STRIDE)          // 67584
#define OFF_WP    0                        // 69632
#define OFF_H     69632                    // + 2*67584 = 204800
#define OFF_B1    204800
#define OFF_B2    205312
#define OFF_W3    205824
#define OFF_PART  206336                   // 2 parity x 128 f32 = 1024
#define OFF_B3    208384
#define ED_SMEM   208512

#define NTILES(E) (((E) + ET - 1) / ET)

__global__ void __launch_bounds__(512, 1)
edge_kernel(const void* __restrict__ ei,
            const float* __restrict__ W2, const float* __restrict__ b1,
            const float* __restrict__ b2, const float* __restrict__ W3,
            const float* __restrict__ b3, float* __restrict__ out, int E)
{
    extern __shared__ __align__(128) char smc[];
    u32 sb = smem_u32(smc);
    float* b1s = (float*)(smc + OFF_B1);
    float* b2s = (float*)(smc + OFF_B2);
    float* w3s = (float*)(smc + OFF_W3);
    float* part = (float*)(smc + OFF_PART);

    int tid = threadIdx.x;
    int lane = tid & 31, w = tid >> 5;
    bool i64 = idx_is_i64(ei);

    if (tid < 128) { b1s[tid] = b1[tid]; b2s[tid] = b2[tid]; w3s[tid] = W3[tid]; }
    if (tid == 0) *(float*)(smc + OFF_B3) = b3[0];
    // Stage W2 into paired tf32 layout (rna): slot (n, ks, q) <- (W[n][8ks+q], W[n][8ks+q+4])
    for (int idx = tid; idx < 128 * 64; idx += 512) {
        int n = idx >> 6, rest = idx & 63;
        int ks = rest >> 2, q = rest & 3;
        u32 v0 = cvt_tf32(W2[n * 128 + ks * 8 + q]);
        u32 v1 = cvt_tf32(W2[n * 128 + ks * 8 + q + 4]);
        *(ull*)(smc + OFF_WP + n * WP_STRIDE + ks * 32 + q * 8) = (ull)v0 | ((ull)v1 << 32);
    }
    __syncthreads();

    int ntiles = NTILES(E);

    if (w < 8) {
        // ========== PRODUCERS (256 thr): prefetch-pipelined line-coalesced gather ==========
        int el0 = w * 16;                  // 16 edges per producer warp
        int r = lane >> 3;                 // edge-in-group 0..3
        int q = lane & 7;                  // float4 index within 128B line
        const float4* b1v = (const float4*)b1s;
        int i = 0;
        for (int t = blockIdx.x; t < ntiles; t += EDGE_GRID, i++) {
            int b = i & 1;
            int myidx;
            {
                int ee = min(t * ET + el0 + (lane & 15), E - 1);
                if (i64) {
                    const long long* qq = (const long long*)ei;
                    myidx = (int)((lane < 16) ? qq[ee] : qq[(size_t)E + ee]);
                } else {
                    const int* qq = (const int*)ei;
                    myidx = (lane < 16) ? qq[ee] : qq[(size_t)E + ee];
                }
            }
            // Prefetch gg=0 gathers into registers BEFORE the buffer-free wait
            float4 av[4], bv[4];
            {
                int s  = __shfl_sync(0xFFFFFFFFu, myidx, r);
                int tg = __shfl_sync(0xFFFFFFFFu, myidx, 16 + r);
                const float4* Ar = (const float4*)g_A + (size_t)s  * 32 + q;
                const float4* Br = (const float4*)g_B + (size_t)tg * 32 + q;
                #pragma unroll
                for (int p = 0; p < 4; p++) { av[p] = Ar[8 * p]; bv[p] = Br[8 * p]; }
            }
            if (i >= NBUF) BAR_SYNC(3 + b, 512);
            #pragma unroll
            for (int gg = 0; gg < 4; gg++) {
                float4 nav[4], nbv[4];
                if (gg < 3) {
                    int jn = (gg + 1) * 4 + r;
                    int s  = __shfl_sync(0xFFFFFFFFu, myidx, jn);
                    int tg = __shfl_sync(0xFFFFFFFFu, myidx, 16 + jn);
                    const float4* Ar = (const float4*)g_A + (size_t)s  * 32 + q;
                    const float4* Br = (const float4*)g_B + (size_t)tg * 32 + q;
                    #pragma unroll
                    for (int p = 0; p < 4; p++) { nav[p] = Ar[8 * p]; nbv[p] = Br[8 * p]; }
                }
                int j = gg * 4 + r;
                char* hh = smc + OFF_H + b * H_TILE + (el0 + j) * H_STRIDE + q * 16;
                #pragma unroll
                for (int p = 0; p < 4; p++) {
                    float4 bi = b1v[q + 8 * p];
                    uint4 hv;
                    hv.x = cvt_tf32(elu_fast(av[p].x + bv[p].x + bi.x));
                    hv.y = cvt_tf32(elu_fast(av[p].y + bv[p].y + bi.y));
                    hv.z = cvt_tf32(elu_fast(av[p].z + bv[p].z + bi.z));
                    hv.w = cvt_tf32(elu_fast(av[p].w + bv[p].w + bi.w));
                    *(uint4*)(hh + p * 128) = hv;
                }
                if (gg < 3) {
                    #pragma unroll
                    for (int p = 0; p < 4; p++) { av[p] = nav[p]; bv[p] = nbv[p]; }
                }
            }
            MEMBAR_CTA();
            BAR_ARRIVE(1 + b, 512);
        }
    } else {
        // ========== CONSUMERS (256 thr): single-pass tf32 + pairwise epilogue ==========
        int cw = w - 8;
        int wm = cw & 3;                  // row block [wm*32,+32)
        int wh = cw >> 2;                 // col half  [wh*64,+64)
        int lg = lane >> 2;               // group id 0..7
        int lq = lane & 3;                // thread-in-group

        u32 bBase = sb + OFF_WP + (wh * 64 + lg) * WP_STRIDE + lq * 8;

        float b3v = *(float*)(smc + OFF_B3);
        int i = 0;
        for (int t = blockIdx.x; t < ntiles; t += EDGE_GRID, i++) {
            int b = i & 1;

            float acc[2][8][4];
            #pragma unroll
            for (int mi = 0; mi < 2; mi++)
                #pragma unroll
                for (int ni = 0; ni < 8; ni++)
                    #pragma unroll
                    for (int qq = 0; qq < 4; qq++) acc[mi][ni][qq] = 0.0f;

            u32 aBase = sb + OFF_H + b * H_TILE + (wm * 32 + lg) * H_STRIDE + lq * 4;

            BAR_SYNC(1 + b, 512);

            #pragma unroll
            for (int ks = 0; ks < 16; ks++) {
                u32 ko = (u32)(ks * 32);
                u32 bb[8][2];
                #pragma unroll
                for (int ni = 0; ni < 8; ni++) {
                    ull v = *(const ull*)(smc + (bBase - sb) + ni * 8 * WP_STRIDE + ko);
                    bb[ni][0] = (u32)v; bb[ni][1] = (u32)(v >> 32);
                }
                #pragma unroll
                for (int mi = 0; mi < 2; mi++) {
                    u32 ab = aBase - sb + mi * 16 * H_STRIDE + ko;
                    u32 a0 = *(const u32*)(smc + ab);
                    u32 a2 = *(const u32*)(smc + ab + 16);
                    u32 a1 = *(const u32*)(smc + ab + 8 * H_STRIDE);
                    u32 a3 = *(const u32*)(smc + ab + 8 * H_STRIDE + 16);
                    #pragma unroll
                    for (int ni = 0; ni < 8; ni++)
                        mma_tf32(acc[mi][ni], a0, a1, a2, a3, bb[ni][0], bb[ni][1]);
                }
            }
            BAR_ARRIVE(3 + b, 512);        // buffer free; epilogue in regs only

            // Per-row partials: pr[mi][half] on lanes lq==0
            float pr[2][2];
            #pragma unroll
            for (int mi = 0; mi < 2; mi++) {
                float p0 = 0.0f, p1 = 0.0f;
                #pragma unroll
                for (int ni = 0; ni < 8; ni++) {
                    int j = wh * 64 + ni * 8 + lq * 2;
                    float w3a = w3s[j], w3b = w3s[j + 1];
                    float b2a = b2s[j], b2b = b2s[j + 1];
                    p0 = fmaf(w3a, elu_fast(acc[mi][ni][0] + b2a), p0);
                    p0 = fmaf(w3b, elu_fast(acc[mi][ni][1] + b2b), p0);
                    p1 = fmaf(w3a, elu_fast(acc[mi][ni][2] + b2a), p1);
                    p1 = fmaf(w3b, elu_fast(acc[mi][ni][3] + b2b), p1);
                }
                p0 += __shfl_xor_sync(0xFFFFFFFFu, p0, 1);
                p0 += __shfl_xor_sync(0xFFFFFFFFu, p0, 2);
                p1 += __shfl_xor_sync(0xFFFFFFFFu, p1, 1);
                p1 += __shfl_xor_sync(0xFFFFFFFFu, p1, 2);
                pr[mi][0] = p0; pr[mi][1] = p1;
            }

            int par = i & 1;
            float* pp = part + par * 128;
            if (wh == 1) {
                if (lq == 0) {
                    #pragma unroll
                    for (int mi = 0; mi < 2; mi++) {
                        int rr = wm * 32 + mi * 16 + lg;
                        pp[rr]     = pr[mi][0];
                        pp[rr + 8] = pr[mi][1];
                    }
                }
                BAR_SYNC(6 + wm, 64);      // pair with wh==0 warp of same wm
            } else {
                BAR_SYNC(6 + wm, 64);
                if (lq == 0) {
                    #pragma unroll
                    for (int mi = 0; mi < 2; mi++) {
                        #pragma unroll
                        for (int hf = 0; hf < 2; hf++) {
                            int rr = wm * 32 + mi * 16 + lg + hf * 8;
                            int e = t * ET + rr;
                            if (e < E) out[e] = pr[mi][hf] + pp[rr] + b3v;
                        }
                    }
                }
            }
        }
    }
}

// ---------------------------------------------------------------------------
extern "C" void kernel_launch(void* const* d_in, const int* in_sizes, int n_in,
                              void* d_out, int out_size)
{
    const float* x  = (const float*)d_in[0];
    const void*  ei = d_in[1];
    const float* W1 = (const float*)d_in[2];
    const float* b1 = (const float*)d_in[3];
    const float* W2 = (const float*)d_in[4];
    const float* b2 = (const float*)d_in[5];
    const float* W3 = (const float*)d_in[6];
    const float* b3 = (const float*)d_in[7];
    float* out = (float*)d_out;

    int N = in_sizes[0] / C;        // 50000
    int E = in_sizes[1] / 2;        // 640000

    cudaFuncSetAttribute(precompute_mma_kernel, cudaFuncAttributeMaxDynamicSharedMemorySize, PC_SMEM);
    cudaFuncSetAttribute(edge_kernel,           cudaFuncAttributeMaxDynamicSharedMemorySize, ED_SMEM);

    precompute_mma_kernel<<<(N + 127) / 128, 512, PC_SMEM>>>(x, W1, N);
    edge_kernel<<<EDGE_GRID, 512, ED_SMEM>>>(ei, W2, b1, b2, W3, b3, out, E);
}